// round 1
// baseline (speedup 1.0000x reference)
#include <cuda_runtime.h>
#include <cuda_bf16.h>
#include <math.h>

#define NT 20000
#define NC 80000
#define NALL 100000
#define HID 128
#define NHD 8
#define DK 16
#define EDG 500000
#define SCALE 0.25f

// ---------------- scratch (device globals; no allocation allowed) ----------------
__device__ float g_y [(size_t)NALL * HID];   // LN1 output, later reused for gelu(h@W1)
__device__ float g_q [(size_t)NALL * HID];
__device__ float g_k [(size_t)NALL * HID];
__device__ float g_v [(size_t)NALL * HID];
__device__ float g_o [(size_t)NALL * HID];   // concat-ordered attention outputs
__device__ float g_x [(size_t)NALL * HID];   // residual after attention block
__device__ float g_h [(size_t)NALL * HID];   // LN2 output
__device__ float g_s1[(size_t)EDG * NHD];    // exp(scores) attn1
__device__ float g_s2[(size_t)EDG * NHD];    // exp(scores) attn2
__device__ float g_z1[(size_t)NT * NHD];     // softmax denom attn1
__device__ float g_z2[(size_t)NC * NHD];     // softmax denom attn2

// ---------------- LayerNorm: one warp per row of 128 ----------------
__global__ __launch_bounds__(256) void ln_kernel(const float* __restrict__ x,
                                                 const float* __restrict__ g,
                                                 const float* __restrict__ b,
                                                 float* __restrict__ y, int n)
{
    int row = blockIdx.x * 8 + (threadIdx.x >> 5);
    if (row >= n) return;
    int lane = threadIdx.x & 31;
    const float4 v = ((const float4*)(x + (size_t)row * HID))[lane];
    float s  = v.x + v.y + v.z + v.w;
    float ss = v.x * v.x + v.y * v.y + v.z * v.z + v.w * v.w;
    #pragma unroll
    for (int off = 16; off > 0; off >>= 1) {
        s  += __shfl_xor_sync(0xffffffffu, s,  off);
        ss += __shfl_xor_sync(0xffffffffu, ss, off);
    }
    float mean = s * (1.0f / HID);
    float var  = ss * (1.0f / HID) - mean * mean;
    float rstd = rsqrtf(var + 1e-5f);
    const float4 gv = ((const float4*)g)[lane];
    const float4 bv = ((const float4*)b)[lane];
    float4 o;
    o.x = (v.x - mean) * rstd * gv.x + bv.x;
    o.y = (v.y - mean) * rstd * gv.y + bv.y;
    o.z = (v.z - mean) * rstd * gv.z + bv.z;
    o.w = (v.w - mean) * rstd * gv.w + bv.w;
    ((float4*)(y + (size_t)row * HID))[lane] = o;
}

// ---------------- GEMM: C[M x 128] = A[M x 128] @ W[128 x 128] + bias (+epilogue) ----
__device__ __forceinline__ float gelu_exact(float x)
{
    return 0.5f * x * (1.0f + erff(x * 0.70710678118654752f));
}

#define EPI_NONE 0
#define EPI_RES  1
#define EPI_GELU 2

template<int EPI>
__global__ __launch_bounds__(256) void gemm128_kernel(const float* __restrict__ A,
                                                      const float* __restrict__ W,
                                                      const float* __restrict__ bias,
                                                      const float* __restrict__ R,
                                                      float* __restrict__ C, int M)
{
    // BM=64, BN=128, BK=32; 256 threads; per-thread tile 8x4
    __shared__ float As[32][68];   // transposed A tile: As[k][m], stride 68 keeps 16B align
    __shared__ float Ws[32][128];

    const int tid = threadIdx.x;
    const int tn  = tid & 31;   // column group (4 cols each)
    const int tm  = tid >> 5;   // row group (8 rows each)
    const int r0  = blockIdx.x * 64;

    float acc[8][4];
    #pragma unroll
    for (int i = 0; i < 8; i++)
        #pragma unroll
        for (int j = 0; j < 4; j++) acc[i][j] = 0.0f;

    for (int k0 = 0; k0 < 128; k0 += 32) {
        // A tile (64 x 32), stored transposed
        #pragma unroll
        for (int i = 0; i < 2; i++) {
            int lin = tid + i * 256;      // 0..511
            int r   = lin >> 3;           // 0..63
            int c4  = lin & 7;            // 0..7
            float4 v = make_float4(0.f, 0.f, 0.f, 0.f);
            if (r0 + r < M) v = *(const float4*)(A + (size_t)(r0 + r) * 128 + k0 + c4 * 4);
            As[c4 * 4 + 0][r] = v.x;
            As[c4 * 4 + 1][r] = v.y;
            As[c4 * 4 + 2][r] = v.z;
            As[c4 * 4 + 3][r] = v.w;
        }
        // W tile (32 x 128)
        #pragma unroll
        for (int i = 0; i < 4; i++) {
            int lin = tid + i * 256;      // 0..1023
            int kr  = lin >> 5;           // 0..31
            int c4  = lin & 31;           // 0..31
            *(float4*)&Ws[kr][c4 * 4] = *(const float4*)(W + (size_t)(k0 + kr) * 128 + c4 * 4);
        }
        __syncthreads();

        #pragma unroll
        for (int kk = 0; kk < 32; kk++) {
            float4 b  = *(const float4*)&Ws[kk][tn * 4];
            float4 a0 = *(const float4*)&As[kk][tm * 8];
            float4 a1 = *(const float4*)&As[kk][tm * 8 + 4];
            float av[8] = {a0.x, a0.y, a0.z, a0.w, a1.x, a1.y, a1.z, a1.w};
            #pragma unroll
            for (int i = 0; i < 8; i++) {
                acc[i][0] += av[i] * b.x;
                acc[i][1] += av[i] * b.y;
                acc[i][2] += av[i] * b.z;
                acc[i][3] += av[i] * b.w;
            }
        }
        __syncthreads();
    }

    const float4 bb = *(const float4*)(bias + tn * 4);
    #pragma unroll
    for (int i = 0; i < 8; i++) {
        int r = r0 + tm * 8 + i;
        if (r >= M) break;
        float4 o;
        o.x = acc[i][0] + bb.x;
        o.y = acc[i][1] + bb.y;
        o.z = acc[i][2] + bb.z;
        o.w = acc[i][3] + bb.w;
        if (EPI == EPI_RES) {
            float4 rv = *(const float4*)(R + (size_t)r * 128 + tn * 4);
            o.x += rv.x; o.y += rv.y; o.z += rv.z; o.w += rv.w;
        } else if (EPI == EPI_GELU) {
            o.x = gelu_exact(o.x);
            o.y = gelu_exact(o.y);
            o.z = gelu_exact(o.z);
            o.w = gelu_exact(o.w);
        }
        *(float4*)(C + (size_t)r * 128 + tn * 4) = o;
    }
}

// ---------------- edge score + exp + segment-sum: one warp per edge ----------------
__global__ __launch_bounds__(256) void edge_score_kernel(const float* __restrict__ Q,
                                                         const float* __restrict__ K,
                                                         const int* __restrict__ row,
                                                         const int* __restrict__ col,
                                                         const float* __restrict__ bias,
                                                         float* __restrict__ ex,
                                                         float* __restrict__ z,
                                                         int qoff, int koff, int ne)
{
    int e = blockIdx.x * 8 + (threadIdx.x >> 5);
    if (e >= ne) return;
    int lane = threadIdx.x & 31;
    int h = lane >> 2, sub = lane & 3;
    int r = row[e], c = col[e];
    const float4 qv = *(const float4*)(Q + (size_t)(r + qoff) * HID + h * 16 + sub * 4);
    const float4 kv = *(const float4*)(K + (size_t)(c + koff) * HID + h * 16 + sub * 4);
    float d = qv.x * kv.x + qv.y * kv.y + qv.z * kv.z + qv.w * kv.w;
    d += __shfl_xor_sync(0xffffffffu, d, 1);
    d += __shfl_xor_sync(0xffffffffu, d, 2);
    if (sub == 0) {
        float sc  = d * SCALE + bias[(size_t)e * NHD + h];
        float exv = __expf(sc);
        ex[(size_t)e * NHD + h] = exv;
        atomicAdd(&z[(size_t)r * NHD + h], exv);
    }
}

// ---------------- edge aggregate: o[row] += (ex/z) * v[col], one warp per edge ------
__global__ __launch_bounds__(256) void edge_aggr_kernel(const float* __restrict__ V,
                                                        const float* __restrict__ ex,
                                                        const float* __restrict__ z,
                                                        const int* __restrict__ row,
                                                        const int* __restrict__ col,
                                                        float* __restrict__ O,
                                                        int koff, int ooff, int ne)
{
    int e = blockIdx.x * 8 + (threadIdx.x >> 5);
    if (e >= ne) return;
    int lane = threadIdx.x & 31;
    int h = lane >> 2, sub = lane & 3;
    int r = row[e], c = col[e];
    float a = ex[(size_t)e * NHD + h] / (z[(size_t)r * NHD + h] + 1e-16f);
    const float4 vv = *(const float4*)(V + (size_t)(c + koff) * HID + h * 16 + sub * 4);
    float* op = O + (size_t)(r + ooff) * HID + h * 16 + sub * 4;
    atomicAdd(op + 0, a * vv.x);
    atomicAdd(op + 1, a * vv.y);
    atomicAdd(op + 2, a * vv.z);
    atomicAdd(op + 3, a * vv.w);
}

// ---------------- host side ----------------
extern "C" void kernel_launch(void* const* d_in, const int* in_sizes, int n_in,
                              void* d_out, int out_size)
{
    const float* x_all    = (const float*)d_in[0];
    const float* bias_c2t = (const float*)d_in[1];
    const float* bias_t2c = (const float*)d_in[2];
    const int*   c2t_row  = (const int*)d_in[3];
    const int*   c2t_col  = (const int*)d_in[4];
    const int*   t2c_row  = (const int*)d_in[5];
    const int*   t2c_col  = (const int*)d_in[6];
    const float* ln1_g    = (const float*)d_in[7];
    const float* ln1_b    = (const float*)d_in[8];
    const float* Wq = (const float*)d_in[9];   const float* bq = (const float*)d_in[10];
    const float* Wk = (const float*)d_in[11];  const float* bk = (const float*)d_in[12];
    const float* Wv = (const float*)d_in[13];  const float* bv = (const float*)d_in[14];
    const float* Wo = (const float*)d_in[15];  const float* bo = (const float*)d_in[16];
    const float* ln2_g = (const float*)d_in[17];
    const float* ln2_b = (const float*)d_in[18];
    const float* W1 = (const float*)d_in[19];  const float* b1 = (const float*)d_in[20];
    const float* W2 = (const float*)d_in[21];  const float* b2 = (const float*)d_in[22];
    float* out = (float*)d_out;

    float *y, *q, *k, *v, *o, *x, *h, *s1, *s2, *z1, *z2;
    cudaGetSymbolAddress((void**)&y,  g_y);
    cudaGetSymbolAddress((void**)&q,  g_q);
    cudaGetSymbolAddress((void**)&k,  g_k);
    cudaGetSymbolAddress((void**)&v,  g_v);
    cudaGetSymbolAddress((void**)&o,  g_o);
    cudaGetSymbolAddress((void**)&x,  g_x);
    cudaGetSymbolAddress((void**)&h,  g_h);
    cudaGetSymbolAddress((void**)&s1, g_s1);
    cudaGetSymbolAddress((void**)&s2, g_s2);
    cudaGetSymbolAddress((void**)&z1, g_z1);
    cudaGetSymbolAddress((void**)&z2, g_z2);

    const int lnGrid   = (NALL + 7) / 8;
    const int gemmGrid = (NALL + 63) / 64;
    const int edgeGrid = (EDG + 7) / 8;

    // LN1
    ln_kernel<<<lnGrid, 256>>>(x_all, ln1_g, ln1_b, y, NALL);

    // Q/K/V for ALL rows (weights shared by both attentions)
    gemm128_kernel<EPI_NONE><<<gemmGrid, 256>>>(y, Wq, bq, nullptr, q, NALL);
    gemm128_kernel<EPI_NONE><<<gemmGrid, 256>>>(y, Wk, bk, nullptr, k, NALL);
    gemm128_kernel<EPI_NONE><<<gemmGrid, 256>>>(y, Wv, bv, nullptr, v, NALL);

    cudaMemsetAsync(z1, 0, (size_t)NT * NHD * sizeof(float), 0);
    cudaMemsetAsync(z2, 0, (size_t)NC * NHD * sizeof(float), 0);
    cudaMemsetAsync(o,  0, (size_t)NALL * HID * sizeof(float), 0);

    // attn1 (ctx2tgt): q from target rows (off 0), k/v from context rows (off NT),
    //                  output rows land at concat offset NC
    edge_score_kernel<<<edgeGrid, 256>>>(q, k, c2t_row, c2t_col, bias_c2t, s1, z1, 0, NT, EDG);
    edge_aggr_kernel <<<edgeGrid, 256>>>(v, s1, z1, c2t_row, c2t_col, o, NT, NC, EDG);

    // attn2 (tgt2cxt): q from context rows (off NT), k/v from target rows (off 0),
    //                  output rows land at concat offset 0
    edge_score_kernel<<<edgeGrid, 256>>>(q, k, t2c_row, t2c_col, bias_t2c, s2, z2, NT, 0, EDG);
    edge_aggr_kernel <<<edgeGrid, 256>>>(v, s2, z2, t2c_row, t2c_col, o, 0, 0, EDG);

    // x = x_all + O @ Wo + bo   (single GEMM covers both attentions' concat)
    gemm128_kernel<EPI_RES><<<gemmGrid, 256>>>(o, Wo, bo, x_all, x, NALL);

    // LN2
    ln_kernel<<<lnGrid, 256>>>(x, ln2_g, ln2_b, h, NALL);

    // t = gelu(h @ W1 + b1)   (reuse g_y)
    gemm128_kernel<EPI_GELU><<<gemmGrid, 256>>>(h, W1, b1, nullptr, y, NALL);

    // out = x + t @ W2 + b2
    gemm128_kernel<EPI_RES><<<gemmGrid, 256>>>(y, W2, b2, x, out, NALL);
}

// round 2
// speedup vs baseline: 1.2344x; 1.2344x over previous
#include <cuda_runtime.h>
#include <cuda_bf16.h>
#include <math.h>
#include <stdint.h>

#define NT 20000
#define NC 80000
#define NALL 100000
#define HID 128
#define NHD 8
#define DK 16
#define EDG 500000
#define SCALE 0.25f

// ---------------- scratch (device globals; no allocation allowed) ----------------
__device__ float g_y [(size_t)NALL * HID];
__device__ float g_q [(size_t)NALL * HID];
__device__ float g_k [(size_t)NALL * HID];
__device__ float g_v [(size_t)NALL * HID];
__device__ float g_o [(size_t)NALL * HID];
__device__ float g_x [(size_t)NALL * HID];
__device__ float g_h [(size_t)NALL * HID];
__device__ float g_s1[(size_t)EDG * NHD];
__device__ float g_s2[(size_t)EDG * NHD];
__device__ float g_z1[(size_t)NT * NHD];
__device__ float g_z2[(size_t)NC * NHD];

// ---------------- LayerNorm: one warp per row of 128 ----------------
__global__ __launch_bounds__(256) void ln_kernel(const float* __restrict__ x,
                                                 const float* __restrict__ g,
                                                 const float* __restrict__ b,
                                                 float* __restrict__ y, int n)
{
    int row = blockIdx.x * 8 + (threadIdx.x >> 5);
    if (row >= n) return;
    int lane = threadIdx.x & 31;
    const float4 v = ((const float4*)(x + (size_t)row * HID))[lane];
    float s  = v.x + v.y + v.z + v.w;
    float ss = v.x * v.x + v.y * v.y + v.z * v.z + v.w * v.w;
    #pragma unroll
    for (int off = 16; off > 0; off >>= 1) {
        s  += __shfl_xor_sync(0xffffffffu, s,  off);
        ss += __shfl_xor_sync(0xffffffffu, ss, off);
    }
    float mean = s * (1.0f / HID);
    float var  = ss * (1.0f / HID) - mean * mean;
    float rstd = rsqrtf(var + 1e-5f);
    const float4 gv = ((const float4*)g)[lane];
    const float4 bv = ((const float4*)b)[lane];
    float4 o;
    o.x = (v.x - mean) * rstd * gv.x + bv.x;
    o.y = (v.y - mean) * rstd * gv.y + bv.y;
    o.z = (v.z - mean) * rstd * gv.z + bv.z;
    o.w = (v.w - mean) * rstd * gv.w + bv.w;
    ((float4*)(y + (size_t)row * HID))[lane] = o;
}

// ---------------- tf32 tensor-core GEMM: C[Mx128] = A[Mx128]@W[128x128]+bias -------
__device__ __forceinline__ float gelu_exact(float x)
{
    return 0.5f * x * (1.0f + erff(x * 0.70710678118654752f));
}

__device__ __forceinline__ uint32_t f2tf(float x)
{
    uint32_t u;
    asm("cvt.rna.tf32.f32 %0, %1;" : "=r"(u) : "f"(x));
    return u;
}

__device__ __forceinline__ void mma_tf32(float c[4], uint32_t a0, uint32_t a1,
                                         uint32_t a2, uint32_t a3,
                                         uint32_t b0, uint32_t b1)
{
    asm volatile(
        "mma.sync.aligned.m16n8k8.row.col.f32.tf32.tf32.f32 "
        "{%0,%1,%2,%3}, {%4,%5,%6,%7}, {%8,%9}, {%0,%1,%2,%3};"
        : "+f"(c[0]), "+f"(c[1]), "+f"(c[2]), "+f"(c[3])
        : "r"(a0), "r"(a1), "r"(a2), "r"(a3), "r"(b0), "r"(b1));
}

#define EPI_NONE 0
#define EPI_RES  1
#define EPI_GELU 2

template<int EPI>
__global__ __launch_bounds__(256) void gemm_tf32_kernel(const float* __restrict__ A,
                                                        const float* __restrict__ W,
                                                        const float* __restrict__ bias,
                                                        const float* __restrict__ R,
                                                        float* __restrict__ C, int M)
{
    __shared__ uint32_t As[128][36];   // [m][k-chunk], stride 36: bank = 4r+c (bijective)
    __shared__ uint32_t Ws[32][136];   // [k][n],       stride 136: bank = 8r+c (bijective)

    const int tid  = threadIdx.x;
    const int warp = tid >> 5;
    const int lane = tid & 31;
    const int r0   = blockIdx.x * 128;

    float acc[16][4];
    #pragma unroll
    for (int n = 0; n < 16; n++)
        #pragma unroll
        for (int j = 0; j < 4; j++) acc[n][j] = 0.0f;

    for (int k0 = 0; k0 < 128; k0 += 32) {
        // stage A chunk (128 x 32)
        #pragma unroll
        for (int i = 0; i < 4; i++) {
            int lin = tid + i * 256;          // 0..1023
            int r   = lin >> 3;               // 0..127
            int c4  = lin & 7;                // 0..7
            float4 v = make_float4(0.f, 0.f, 0.f, 0.f);
            if (r0 + r < M) v = *(const float4*)(A + (size_t)(r0 + r) * 128 + k0 + c4 * 4);
            As[r][c4 * 4 + 0] = f2tf(v.x);
            As[r][c4 * 4 + 1] = f2tf(v.y);
            As[r][c4 * 4 + 2] = f2tf(v.z);
            As[r][c4 * 4 + 3] = f2tf(v.w);
        }
        // stage W chunk (32 x 128)
        #pragma unroll
        for (int i = 0; i < 4; i++) {
            int lin = tid + i * 256;          // 0..1023
            int kr  = lin >> 5;               // 0..31
            int c4  = lin & 31;               // 0..31
            float4 v = *(const float4*)(W + (size_t)(k0 + kr) * 128 + c4 * 4);
            Ws[kr][c4 * 4 + 0] = f2tf(v.x);
            Ws[kr][c4 * 4 + 1] = f2tf(v.y);
            Ws[kr][c4 * 4 + 2] = f2tf(v.z);
            Ws[kr][c4 * 4 + 3] = f2tf(v.w);
        }
        __syncthreads();

        const int ar = warp * 16 + (lane >> 2);
        #pragma unroll
        for (int kk = 0; kk < 32; kk += 8) {
            const int ac = kk + (lane & 3);
            uint32_t a0 = As[ar][ac];
            uint32_t a1 = As[ar + 8][ac];
            uint32_t a2 = As[ar][ac + 4];
            uint32_t a3 = As[ar + 8][ac + 4];
            const int br = kk + (lane & 3);
            const int bc = lane >> 2;
            #pragma unroll
            for (int n = 0; n < 16; n++) {
                uint32_t b0 = Ws[br][n * 8 + bc];
                uint32_t b1 = Ws[br + 4][n * 8 + bc];
                mma_tf32(acc[n], a0, a1, a2, a3, b0, b1);
            }
        }
        __syncthreads();
    }

    // epilogue: c0,c1 -> (r, col..col+1); c2,c3 -> (r+8, col..col+1)
    const int r  = r0 + warp * 16 + (lane >> 2);
    const int cb = 2 * (lane & 3);
    #pragma unroll
    for (int n = 0; n < 16; n++) {
        const int col = n * 8 + cb;
        float2 bb = *(const float2*)(bias + col);
        float v0 = acc[n][0] + bb.x, v1 = acc[n][1] + bb.y;
        float v2 = acc[n][2] + bb.x, v3 = acc[n][3] + bb.y;
        if (EPI == EPI_GELU) {
            v0 = gelu_exact(v0); v1 = gelu_exact(v1);
            v2 = gelu_exact(v2); v3 = gelu_exact(v3);
        }
        if (r < M) {
            if (EPI == EPI_RES) {
                float2 rv = *(const float2*)(R + (size_t)r * 128 + col);
                v0 += rv.x; v1 += rv.y;
            }
            *(float2*)(C + (size_t)r * 128 + col) = make_float2(v0, v1);
        }
        if (r + 8 < M) {
            if (EPI == EPI_RES) {
                float2 rv = *(const float2*)(R + (size_t)(r + 8) * 128 + col);
                v2 += rv.x; v3 += rv.y;
            }
            *(float2*)(C + (size_t)(r + 8) * 128 + col) = make_float2(v2, v3);
        }
    }
}

// ---------------- edge score + exp + segment-sum: one warp per edge ----------------
__global__ __launch_bounds__(256) void edge_score_kernel(const float* __restrict__ Q,
                                                         const float* __restrict__ K,
                                                         const int* __restrict__ row,
                                                         const int* __restrict__ col,
                                                         const float* __restrict__ bias,
                                                         float* __restrict__ ex,
                                                         float* __restrict__ z,
                                                         int qoff, int koff, int ne)
{
    int e = blockIdx.x * 8 + (threadIdx.x >> 5);
    if (e >= ne) return;
    int lane = threadIdx.x & 31;
    int h = lane >> 2, sub = lane & 3;
    int r = row[e], c = col[e];
    const float4 qv = *(const float4*)(Q + (size_t)(r + qoff) * HID + h * 16 + sub * 4);
    const float4 kv = *(const float4*)(K + (size_t)(c + koff) * HID + h * 16 + sub * 4);
    float d = qv.x * kv.x + qv.y * kv.y + qv.z * kv.z + qv.w * kv.w;
    d += __shfl_xor_sync(0xffffffffu, d, 1);
    d += __shfl_xor_sync(0xffffffffu, d, 2);
    if (sub == 0) {
        float sc  = d * SCALE + bias[(size_t)e * NHD + h];
        float exv = __expf(sc);
        ex[(size_t)e * NHD + h] = exv;
        atomicAdd(&z[(size_t)r * NHD + h], exv);
    }
}

// ---------------- edge aggregate: o[row] += (ex/z) * v[col] ------------------------
__global__ __launch_bounds__(256) void edge_aggr_kernel(const float* __restrict__ V,
                                                        const float* __restrict__ ex,
                                                        const float* __restrict__ z,
                                                        const int* __restrict__ row,
                                                        const int* __restrict__ col,
                                                        float* __restrict__ O,
                                                        int koff, int ooff, int ne)
{
    int e = blockIdx.x * 8 + (threadIdx.x >> 5);
    if (e >= ne) return;
    int lane = threadIdx.x & 31;
    int h = lane >> 2, sub = lane & 3;
    int r = row[e], c = col[e];
    float a = ex[(size_t)e * NHD + h] / (z[(size_t)r * NHD + h] + 1e-16f);
    const float4 vv = *(const float4*)(V + (size_t)(c + koff) * HID + h * 16 + sub * 4);
    float* op = O + (size_t)(r + ooff) * HID + h * 16 + sub * 4;
    atomicAdd(op + 0, a * vv.x);
    atomicAdd(op + 1, a * vv.y);
    atomicAdd(op + 2, a * vv.z);
    atomicAdd(op + 3, a * vv.w);
}

// ---------------- host side ----------------
extern "C" void kernel_launch(void* const* d_in, const int* in_sizes, int n_in,
                              void* d_out, int out_size)
{
    const float* x_all    = (const float*)d_in[0];
    const float* bias_c2t = (const float*)d_in[1];
    const float* bias_t2c = (const float*)d_in[2];
    const int*   c2t_row  = (const int*)d_in[3];
    const int*   c2t_col  = (const int*)d_in[4];
    const int*   t2c_row  = (const int*)d_in[5];
    const int*   t2c_col  = (const int*)d_in[6];
    const float* ln1_g    = (const float*)d_in[7];
    const float* ln1_b    = (const float*)d_in[8];
    const float* Wq = (const float*)d_in[9];   const float* bq = (const float*)d_in[10];
    const float* Wk = (const float*)d_in[11];  const float* bk = (const float*)d_in[12];
    const float* Wv = (const float*)d_in[13];  const float* bv = (const float*)d_in[14];
    const float* Wo = (const float*)d_in[15];  const float* bo = (const float*)d_in[16];
    const float* ln2_g = (const float*)d_in[17];
    const float* ln2_b = (const float*)d_in[18];
    const float* W1 = (const float*)d_in[19];  const float* b1 = (const float*)d_in[20];
    const float* W2 = (const float*)d_in[21];  const float* b2 = (const float*)d_in[22];
    float* out = (float*)d_out;

    float *y, *q, *k, *v, *o, *x, *h, *s1, *s2, *z1, *z2;
    cudaGetSymbolAddress((void**)&y,  g_y);
    cudaGetSymbolAddress((void**)&q,  g_q);
    cudaGetSymbolAddress((void**)&k,  g_k);
    cudaGetSymbolAddress((void**)&v,  g_v);
    cudaGetSymbolAddress((void**)&o,  g_o);
    cudaGetSymbolAddress((void**)&x,  g_x);
    cudaGetSymbolAddress((void**)&h,  g_h);
    cudaGetSymbolAddress((void**)&s1, g_s1);
    cudaGetSymbolAddress((void**)&s2, g_s2);
    cudaGetSymbolAddress((void**)&z1, g_z1);
    cudaGetSymbolAddress((void**)&z2, g_z2);

    const int lnGrid   = (NALL + 7) / 8;
    const int gemmGrid = (NALL + 127) / 128;
    const int edgeGrid = (EDG + 7) / 8;

    ln_kernel<<<lnGrid, 256>>>(x_all, ln1_g, ln1_b, y, NALL);

    gemm_tf32_kernel<EPI_NONE><<<gemmGrid, 256>>>(y, Wq, bq, nullptr, q, NALL);
    gemm_tf32_kernel<EPI_NONE><<<gemmGrid, 256>>>(y, Wk, bk, nullptr, k, NALL);
    gemm_tf32_kernel<EPI_NONE><<<gemmGrid, 256>>>(y, Wv, bv, nullptr, v, NALL);

    cudaMemsetAsync(z1, 0, (size_t)NT * NHD * sizeof(float), 0);
    cudaMemsetAsync(z2, 0, (size_t)NC * NHD * sizeof(float), 0);
    cudaMemsetAsync(o,  0, (size_t)NALL * HID * sizeof(float), 0);

    edge_score_kernel<<<edgeGrid, 256>>>(q, k, c2t_row, c2t_col, bias_c2t, s1, z1, 0, NT, EDG);
    edge_aggr_kernel <<<edgeGrid, 256>>>(v, s1, z1, c2t_row, c2t_col, o, NT, NC, EDG);

    edge_score_kernel<<<edgeGrid, 256>>>(q, k, t2c_row, t2c_col, bias_t2c, s2, z2, NT, 0, EDG);
    edge_aggr_kernel <<<edgeGrid, 256>>>(v, s2, z2, t2c_row, t2c_col, o, 0, 0, EDG);

    gemm_tf32_kernel<EPI_RES><<<gemmGrid, 256>>>(o, Wo, bo, x_all, x, NALL);

    ln_kernel<<<lnGrid, 256>>>(x, ln2_g, ln2_b, h, NALL);

    gemm_tf32_kernel<EPI_GELU><<<gemmGrid, 256>>>(h, W1, b1, nullptr, y, NALL);

    gemm_tf32_kernel<EPI_RES><<<gemmGrid, 256>>>(y, W2, b2, x, out, NALL);
}

// round 3
// speedup vs baseline: 1.6650x; 1.3489x over previous
#include <cuda_runtime.h>
#include <cuda_bf16.h>
#include <math.h>
#include <stdint.h>

#define NT 20000
#define NC 80000
#define NALL 100000
#define HID 128
#define NHD 8
#define EDG 500000
#define SCALE 0.25f

typedef __nv_bfloat16 bf16;
typedef __nv_bfloat162 bf162;

// ---------------- scratch ----------------
__device__ float g_y [(size_t)NALL * HID];   // LN1 out / gelu(h@W1)
__device__ bf16  g_qb[(size_t)NALL * HID];
__device__ bf16  g_kb[(size_t)NALL * HID];
__device__ bf16  g_vb[(size_t)NALL * HID];
__device__ float g_o [(size_t)NALL * HID];   // unnormalized attn num, then normalized
__device__ float g_x [(size_t)NALL * HID];
__device__ float g_h [(size_t)NALL * HID];
__device__ float g_z1[(size_t)NT * NHD];
__device__ float g_z2[(size_t)NC * NHD];

// ---------------- LayerNorm ----------------
__global__ __launch_bounds__(256) void ln_kernel(const float* __restrict__ x,
                                                 const float* __restrict__ g,
                                                 const float* __restrict__ b,
                                                 float* __restrict__ y, int n)
{
    int row = blockIdx.x * 8 + (threadIdx.x >> 5);
    if (row >= n) return;
    int lane = threadIdx.x & 31;
    const float4 v = ((const float4*)(x + (size_t)row * HID))[lane];
    float s  = v.x + v.y + v.z + v.w;
    float ss = v.x * v.x + v.y * v.y + v.z * v.z + v.w * v.w;
    #pragma unroll
    for (int off = 16; off > 0; off >>= 1) {
        s  += __shfl_xor_sync(0xffffffffu, s,  off);
        ss += __shfl_xor_sync(0xffffffffu, ss, off);
    }
    float mean = s * (1.0f / HID);
    float var  = ss * (1.0f / HID) - mean * mean;
    float rstd = rsqrtf(var + 1e-5f);
    const float4 gv = ((const float4*)g)[lane];
    const float4 bv = ((const float4*)b)[lane];
    float4 o;
    o.x = (v.x - mean) * rstd * gv.x + bv.x;
    o.y = (v.y - mean) * rstd * gv.y + bv.y;
    o.z = (v.z - mean) * rstd * gv.z + bv.z;
    o.w = (v.w - mean) * rstd * gv.w + bv.w;
    ((float4*)(y + (size_t)row * HID))[lane] = o;
}

// ---------------- GEMM helpers ----------------
__device__ __forceinline__ float gelu_exact(float x)
{
    return 0.5f * x * (1.0f + erff(x * 0.70710678118654752f));
}

__device__ __forceinline__ void mma_tf32(float c[4], uint32_t a0, uint32_t a1,
                                         uint32_t a2, uint32_t a3,
                                         uint32_t b0, uint32_t b1)
{
    asm volatile(
        "mma.sync.aligned.m16n8k8.row.col.f32.tf32.tf32.f32 "
        "{%0,%1,%2,%3}, {%4,%5,%6,%7}, {%8,%9}, {%0,%1,%2,%3};"
        : "+f"(c[0]), "+f"(c[1]), "+f"(c[2]), "+f"(c[3])
        : "r"(a0), "r"(a1), "r"(a2), "r"(a3), "r"(b0), "r"(b1));
}

__device__ __forceinline__ void cp16(uint32_t dst, const void* src, bool pred)
{
    asm volatile("cp.async.cg.shared.global [%0], [%1], 16, %2;\n"
                 :: "r"(dst), "l"(src), "r"(pred ? 16 : 0));
}
__device__ __forceinline__ void cp_commit() { asm volatile("cp.async.commit_group;\n"); }
__device__ __forceinline__ void cp_wait1()  { asm volatile("cp.async.wait_group 1;\n"); }

__device__ __forceinline__ void store2(float* C, size_t idx, float a, float b)
{
    *(float2*)(C + idx) = make_float2(a, b);
}
__device__ __forceinline__ void store2(bf16* C, size_t idx, float a, float b)
{
    *(bf162*)(C + idx) = __floats2bfloat162_rn(a, b);
}

#define EPI_NONE 0
#define EPI_RES  1
#define EPI_GELU 2

// A-stage: 128x32 fp32, row stride 36 (frag bank = 4r+c, conflict-free)
// W-stage: 32x128 fp32, row stride 136 (frag bank = 8r+c, conflict-free)
#define A_STG (128 * 36)
#define W_STG (32 * 136)
#define GEMM_SMEM ((2 * A_STG + 2 * W_STG) * sizeof(float))

template<int EPI, typename OutT>
__global__ __launch_bounds__(256) void gemm_tc_kernel(const float* __restrict__ A,
                                                      const float* __restrict__ W,
                                                      const float* __restrict__ bias,
                                                      const float* __restrict__ R,
                                                      OutT* __restrict__ C, int M)
{
    extern __shared__ float smem[];
    float* As = smem;                 // [2][128][36]
    float* Ws = smem + 2 * A_STG;     // [2][32][136]

    const int tid  = threadIdx.x;
    const int warp = tid >> 5;
    const int lane = tid & 31;
    const int r0   = blockIdx.x * 128;
    const uint32_t smem_base = (uint32_t)__cvta_generic_to_shared(smem);

    float acc[16][4];
    #pragma unroll
    for (int n = 0; n < 16; n++)
        #pragma unroll
        for (int j = 0; j < 4; j++) acc[n][j] = 0.0f;

    auto stage = [&](int s, int k0) {
        #pragma unroll
        for (int i = 0; i < 4; i++) {
            int lin = tid + i * 256;           // 0..1023
            int r   = lin >> 3;                // 0..127
            int c4  = lin & 7;                 // 0..7
            uint32_t dst = smem_base + (uint32_t)((s * A_STG + r * 36 + c4 * 4) * 4);
            cp16(dst, A + (size_t)(r0 + r) * 128 + k0 + c4 * 4, r0 + r < M);
        }
        #pragma unroll
        for (int i = 0; i < 4; i++) {
            int lin = tid + i * 256;
            int kr  = lin >> 5;                // 0..31
            int c4  = lin & 31;                // 0..31
            uint32_t dst = smem_base + (uint32_t)((2 * A_STG + s * W_STG + kr * 136 + c4 * 4) * 4);
            cp16(dst, W + (size_t)(k0 + kr) * 128 + c4 * 4, true);
        }
    };

    stage(0, 0);
    cp_commit();

    #pragma unroll
    for (int kc = 0; kc < 4; kc++) {
        if (kc < 3) stage((kc + 1) & 1, (kc + 1) * 32);
        cp_commit();
        cp_wait1();
        __syncthreads();

        const float* Ab = As + (kc & 1) * A_STG;
        const float* Wb = Ws + (kc & 1) * W_STG;
        const int ar = warp * 16 + (lane >> 2);
        #pragma unroll
        for (int kk = 0; kk < 32; kk += 8) {
            const int ac = kk + (lane & 3);
            uint32_t a0 = __float_as_uint(Ab[ar * 36 + ac]);
            uint32_t a1 = __float_as_uint(Ab[(ar + 8) * 36 + ac]);
            uint32_t a2 = __float_as_uint(Ab[ar * 36 + ac + 4]);
            uint32_t a3 = __float_as_uint(Ab[(ar + 8) * 36 + ac + 4]);
            const int br = kk + (lane & 3);
            const int bc = lane >> 2;
            #pragma unroll
            for (int n = 0; n < 16; n++) {
                uint32_t b0 = __float_as_uint(Wb[br * 136 + n * 8 + bc]);
                uint32_t b1 = __float_as_uint(Wb[(br + 4) * 136 + n * 8 + bc]);
                mma_tf32(acc[n], a0, a1, a2, a3, b0, b1);
            }
        }
        __syncthreads();
    }

    const int r  = r0 + warp * 16 + (lane >> 2);
    const int cb = 2 * (lane & 3);
    #pragma unroll
    for (int n = 0; n < 16; n++) {
        const int col = n * 8 + cb;
        float2 bb = *(const float2*)(bias + col);
        float v0 = acc[n][0] + bb.x, v1 = acc[n][1] + bb.y;
        float v2 = acc[n][2] + bb.x, v3 = acc[n][3] + bb.y;
        if (EPI == EPI_GELU) {
            v0 = gelu_exact(v0); v1 = gelu_exact(v1);
            v2 = gelu_exact(v2); v3 = gelu_exact(v3);
        }
        if (r < M) {
            float a0 = v0, a1 = v1;
            if (EPI == EPI_RES) {
                float2 rv = *(const float2*)(R + (size_t)r * 128 + col);
                a0 += rv.x; a1 += rv.y;
            }
            store2(C, (size_t)r * 128 + col, a0, a1);
        }
        if (r + 8 < M) {
            float a2 = v2, a3 = v3;
            if (EPI == EPI_RES) {
                float2 rv = *(const float2*)(R + (size_t)(r + 8) * 128 + col);
                a2 += rv.x; a3 += rv.y;
            }
            store2(C, (size_t)(r + 8) * 128 + col, a2, a3);
        }
    }
}

// ---------------- fused edge pass: num[r] += ex * v[c];  z[r] += ex ----------------
__global__ __launch_bounds__(256) void edge_attn_kernel(const bf16* __restrict__ Q,
                                                        const bf16* __restrict__ K,
                                                        const bf16* __restrict__ V,
                                                        const int* __restrict__ row,
                                                        const int* __restrict__ col,
                                                        const float* __restrict__ bias,
                                                        float* __restrict__ num,
                                                        float* __restrict__ z,
                                                        int qoff, int koff, int ooff, int ne)
{
    int e = blockIdx.x * 8 + (threadIdx.x >> 5);
    if (e >= ne) return;
    int lane = threadIdx.x & 31;
    int h = lane >> 2;
    int r = row[e], c = col[e];

    uint2 qraw = *((const uint2*)(Q + (size_t)(r + qoff) * HID) + lane);
    uint2 kraw = *((const uint2*)(K + (size_t)(c + koff) * HID) + lane);
    float2 qa = __bfloat1622float2(*(bf162*)&qraw.x);
    float2 qb = __bfloat1622float2(*(bf162*)&qraw.y);
    float2 ka = __bfloat1622float2(*(bf162*)&kraw.x);
    float2 kb = __bfloat1622float2(*(bf162*)&kraw.y);
    float d = qa.x * ka.x + qa.y * ka.y + qb.x * kb.x + qb.y * kb.y;
    d += __shfl_xor_sync(0xffffffffu, d, 1);
    d += __shfl_xor_sync(0xffffffffu, d, 2);

    float sc = d * SCALE + __ldg(&bias[(size_t)e * NHD + h]);
    float ex = __expf(sc);
    if ((lane & 3) == 0) atomicAdd(&z[(size_t)r * NHD + h], ex);

    uint2 vraw = *((const uint2*)(V + (size_t)(c + koff) * HID) + lane);
    float2 va = __bfloat1622float2(*(bf162*)&vraw.x);
    float2 vb = __bfloat1622float2(*(bf162*)&vraw.y);
    float* op = num + (size_t)(r + ooff) * HID + lane * 4;
    atomicAdd(op + 0, ex * va.x);
    atomicAdd(op + 1, ex * va.y);
    atomicAdd(op + 2, ex * vb.x);
    atomicAdd(op + 3, ex * vb.y);
}

// ---------------- normalize: o = num / (z + eps) ----------------
__global__ __launch_bounds__(256) void norm_kernel(float* __restrict__ o,
                                                   const float* __restrict__ z, int n)
{
    int row = blockIdx.x * 8 + (threadIdx.x >> 5);
    if (row >= n) return;
    int lane = threadIdx.x & 31;
    float rz = 1.0f / (z[(size_t)row * NHD + (lane >> 2)] + 1e-16f);
    float4* p = (float4*)(o + (size_t)row * HID) + lane;
    float4 v = *p;
    v.x *= rz; v.y *= rz; v.z *= rz; v.w *= rz;
    *p = v;
}

// ---------------- host ----------------
extern "C" void kernel_launch(void* const* d_in, const int* in_sizes, int n_in,
                              void* d_out, int out_size)
{
    const float* x_all    = (const float*)d_in[0];
    const float* bias_c2t = (const float*)d_in[1];
    const float* bias_t2c = (const float*)d_in[2];
    const int*   c2t_row  = (const int*)d_in[3];
    const int*   c2t_col  = (const int*)d_in[4];
    const int*   t2c_row  = (const int*)d_in[5];
    const int*   t2c_col  = (const int*)d_in[6];
    const float* ln1_g    = (const float*)d_in[7];
    const float* ln1_b    = (const float*)d_in[8];
    const float* Wq = (const float*)d_in[9];   const float* bq = (const float*)d_in[10];
    const float* Wk = (const float*)d_in[11];  const float* bk = (const float*)d_in[12];
    const float* Wv = (const float*)d_in[13];  const float* bv = (const float*)d_in[14];
    const float* Wo = (const float*)d_in[15];  const float* bo = (const float*)d_in[16];
    const float* ln2_g = (const float*)d_in[17];
    const float* ln2_b = (const float*)d_in[18];
    const float* W1 = (const float*)d_in[19];  const float* b1 = (const float*)d_in[20];
    const float* W2 = (const float*)d_in[21];  const float* b2 = (const float*)d_in[22];
    float* out = (float*)d_out;

    float *y, *o, *x, *h, *z1, *z2;
    bf16 *qb, *kb, *vb;
    cudaGetSymbolAddress((void**)&y,  g_y);
    cudaGetSymbolAddress((void**)&qb, g_qb);
    cudaGetSymbolAddress((void**)&kb, g_kb);
    cudaGetSymbolAddress((void**)&vb, g_vb);
    cudaGetSymbolAddress((void**)&o,  g_o);
    cudaGetSymbolAddress((void**)&x,  g_x);
    cudaGetSymbolAddress((void**)&h,  g_h);
    cudaGetSymbolAddress((void**)&z1, g_z1);
    cudaGetSymbolAddress((void**)&z2, g_z2);

    cudaFuncSetAttribute(gemm_tc_kernel<EPI_NONE, bf16>,
                         cudaFuncAttributeMaxDynamicSharedMemorySize, GEMM_SMEM);
    cudaFuncSetAttribute(gemm_tc_kernel<EPI_RES, float>,
                         cudaFuncAttributeMaxDynamicSharedMemorySize, GEMM_SMEM);
    cudaFuncSetAttribute(gemm_tc_kernel<EPI_GELU, float>,
                         cudaFuncAttributeMaxDynamicSharedMemorySize, GEMM_SMEM);

    const int lnGrid   = (NALL + 7) / 8;
    const int gemmGrid = (NALL + 127) / 128;
    const int edgeGrid = (EDG + 7) / 8;

    // LN1
    ln_kernel<<<lnGrid, 256>>>(x_all, ln1_g, ln1_b, y, NALL);

    // QKV (bf16 outputs)
    gemm_tc_kernel<EPI_NONE, bf16><<<gemmGrid, 256, GEMM_SMEM>>>(y, Wq, bq, nullptr, qb, NALL);
    gemm_tc_kernel<EPI_NONE, bf16><<<gemmGrid, 256, GEMM_SMEM>>>(y, Wk, bk, nullptr, kb, NALL);
    gemm_tc_kernel<EPI_NONE, bf16><<<gemmGrid, 256, GEMM_SMEM>>>(y, Wv, bv, nullptr, vb, NALL);

    cudaMemsetAsync(z1, 0, (size_t)NT * NHD * sizeof(float), 0);
    cudaMemsetAsync(z2, 0, (size_t)NC * NHD * sizeof(float), 0);
    cudaMemsetAsync(o,  0, (size_t)NALL * HID * sizeof(float), 0);

    // attn1 (ctx2tgt): q=target rows, k/v=context rows, out rows at concat offset NC
    edge_attn_kernel<<<edgeGrid, 256>>>(qb, kb, vb, c2t_row, c2t_col, bias_c2t,
                                        o, z1, 0, NT, NC, EDG);
    // attn2 (tgt2cxt): q=context rows, k/v=target rows, out rows at concat offset 0
    edge_attn_kernel<<<edgeGrid, 256>>>(qb, kb, vb, t2c_row, t2c_col, bias_t2c,
                                        o, z2, NT, 0, 0, EDG);

    norm_kernel<<<(NC + 7) / 8, 256>>>(o, z2, NC);
    norm_kernel<<<(NT + 7) / 8, 256>>>(o + (size_t)NC * HID, z1, NT);

    // x = x_all + O @ Wo + bo
    gemm_tc_kernel<EPI_RES, float><<<gemmGrid, 256, GEMM_SMEM>>>(o, Wo, bo, x_all, x, NALL);

    // LN2
    ln_kernel<<<lnGrid, 256>>>(x, ln2_g, ln2_b, h, NALL);

    // y = gelu(h @ W1 + b1)
    gemm_tc_kernel<EPI_GELU, float><<<gemmGrid, 256, GEMM_SMEM>>>(h, W1, b1, nullptr, y, NALL);

    // out = x + y @ W2 + b2
    gemm_tc_kernel<EPI_RES, float><<<gemmGrid, 256, GEMM_SMEM>>>(y, W2, b2, x, out, NALL);
}

// round 4
// speedup vs baseline: 2.1505x; 1.2916x over previous
#include <cuda_runtime.h>
#include <cuda_bf16.h>
#include <math.h>
#include <stdint.h>

#define NT 20000
#define NC 80000
#define NALL 100000
#define HID 128
#define NHD 8
#define EDG 500000
#define SCALE 0.25f

typedef __nv_bfloat16 bf16;
typedef __nv_bfloat162 bf162;

// ---------------- scratch ----------------
__device__ float g_y [(size_t)NALL * HID];
__device__ bf16  g_qb[(size_t)NALL * HID];
__device__ bf16  g_kb[(size_t)NALL * HID];
__device__ bf16  g_vb[(size_t)NALL * HID];
__device__ float g_o [(size_t)NALL * HID];
__device__ float g_x [(size_t)NALL * HID];
__device__ float g_h [(size_t)NALL * HID];
__device__ float g_z1[(size_t)NT * NHD];
__device__ float g_z2[(size_t)NC * NHD];

// ---------------- LayerNorm ----------------
__global__ __launch_bounds__(256) void ln_kernel(const float* __restrict__ x,
                                                 const float* __restrict__ g,
                                                 const float* __restrict__ b,
                                                 float* __restrict__ y, int n)
{
    int row = blockIdx.x * 8 + (threadIdx.x >> 5);
    if (row >= n) return;
    int lane = threadIdx.x & 31;
    const float4 v = ((const float4*)(x + (size_t)row * HID))[lane];
    float s  = v.x + v.y + v.z + v.w;
    float ss = v.x * v.x + v.y * v.y + v.z * v.z + v.w * v.w;
    #pragma unroll
    for (int off = 16; off > 0; off >>= 1) {
        s  += __shfl_xor_sync(0xffffffffu, s,  off);
        ss += __shfl_xor_sync(0xffffffffu, ss, off);
    }
    float mean = s * (1.0f / HID);
    float var  = ss * (1.0f / HID) - mean * mean;
    float rstd = rsqrtf(var + 1e-5f);
    const float4 gv = ((const float4*)g)[lane];
    const float4 bv = ((const float4*)b)[lane];
    float4 o;
    o.x = (v.x - mean) * rstd * gv.x + bv.x;
    o.y = (v.y - mean) * rstd * gv.y + bv.y;
    o.z = (v.z - mean) * rstd * gv.z + bv.z;
    o.w = (v.w - mean) * rstd * gv.w + bv.w;
    ((float4*)(y + (size_t)row * HID))[lane] = o;
}

// ---------------- common GEMM helpers ----------------
__device__ __forceinline__ float gelu_exact(float x)
{
    return 0.5f * x * (1.0f + erff(x * 0.70710678118654752f));
}

__device__ __forceinline__ void mma_tf32(float c[4], uint32_t a0, uint32_t a1,
                                         uint32_t a2, uint32_t a3,
                                         uint32_t b0, uint32_t b1)
{
    asm volatile(
        "mma.sync.aligned.m16n8k8.row.col.f32.tf32.tf32.f32 "
        "{%0,%1,%2,%3}, {%4,%5,%6,%7}, {%8,%9}, {%0,%1,%2,%3};"
        : "+f"(c[0]), "+f"(c[1]), "+f"(c[2]), "+f"(c[3])
        : "r"(a0), "r"(a1), "r"(a2), "r"(a3), "r"(b0), "r"(b1));
}

__device__ __forceinline__ void cp16(uint32_t dst, const void* src, bool pred)
{
    asm volatile("cp.async.cg.shared.global [%0], [%1], 16, %2;\n"
                 :: "r"(dst), "l"(src), "r"(pred ? 16 : 0));
}
__device__ __forceinline__ void cp_commit() { asm volatile("cp.async.commit_group;\n"); }
__device__ __forceinline__ void cp_wait1()  { asm volatile("cp.async.wait_group 1;\n"); }

__device__ __forceinline__ void store2(float* C, size_t idx, float a, float b)
{
    *(float2*)(C + idx) = make_float2(a, b);
}
__device__ __forceinline__ void store2(bf16* C, size_t idx, float a, float b)
{
    *(bf162*)(C + idx) = __floats2bfloat162_rn(a, b);
}

#define EPI_NONE 0
#define EPI_RES  1
#define EPI_GELU 2

// ============ fused QKV GEMM: A staged once, 3 weights ============
#define QA_STR 132
#define QA_SZ  (128 * QA_STR)
#define QW_STG (32 * 136)
#define QKV_SMEM ((QA_SZ + 2 * QW_STG) * sizeof(float))

__global__ __launch_bounds__(256) void qkv_kernel(const float* __restrict__ A,
                                                  const float* __restrict__ Wq,
                                                  const float* __restrict__ Wk,
                                                  const float* __restrict__ Wv,
                                                  const float* __restrict__ bq,
                                                  const float* __restrict__ bk,
                                                  const float* __restrict__ bv,
                                                  bf16* __restrict__ Oq,
                                                  bf16* __restrict__ Ok,
                                                  bf16* __restrict__ Ov, int M)
{
    extern __shared__ float smem[];
    float* As = smem;                 // [128][132]
    float* Ws = smem + QA_SZ;         // [2][32][136]

    const float* Wp[3] = {Wq, Wk, Wv};
    const float* bp[3] = {bq, bk, bv};
    bf16*        op[3] = {Oq, Ok, Ov};

    const int tid  = threadIdx.x;
    const int warp = tid >> 5;
    const int lane = tid & 31;
    const int r0   = blockIdx.x * 128;
    const uint32_t smem_base = (uint32_t)__cvta_generic_to_shared(smem);

    auto stageW = [&](int s, const float* W, int k0) {
        #pragma unroll
        for (int i = 0; i < 4; i++) {
            int lin = tid + i * 256;
            int kr  = lin >> 5;
            int c4  = lin & 31;
            uint32_t dst = smem_base + (uint32_t)((QA_SZ + s * QW_STG + kr * 136 + c4 * 4) * 4);
            cp16(dst, W + (size_t)(k0 + kr) * 128 + c4 * 4, true);
        }
    };

    // stage full A (128x128) + W[0] chunk 0, one group
    #pragma unroll
    for (int i = 0; i < 16; i++) {
        int lin = tid + i * 256;               // 0..4095
        int r   = lin >> 5;                    // 0..127
        int c4  = lin & 31;                    // 0..31
        uint32_t dst = smem_base + (uint32_t)((r * QA_STR + c4 * 4) * 4);
        cp16(dst, A + (size_t)(r0 + r) * 128 + c4 * 4, r0 + r < M);
    }
    stageW(0, Wq, 0);
    cp_commit();

    const int ar = warp * 16 + (lane >> 2);
    #pragma unroll
    for (int w = 0; w < 3; w++) {
        float acc[16][4];
        #pragma unroll
        for (int n = 0; n < 16; n++)
            #pragma unroll
            for (int j = 0; j < 4; j++) acc[n][j] = 0.0f;

        #pragma unroll
        for (int kc = 0; kc < 4; kc++) {
            int t = w * 4 + kc;
            if (t < 11) {
                int nt = t + 1;
                stageW(nt & 1, Wp[nt >> 2], (nt & 3) * 32);
            }
            cp_commit();
            cp_wait1();
            __syncthreads();

            const float* Ab = As + kc * 32;
            const float* Wb = Ws + (t & 1) * QW_STG;
            #pragma unroll
            for (int kk = 0; kk < 32; kk += 8) {
                const int ac = kk + (lane & 3);
                uint32_t a0 = __float_as_uint(Ab[ar * QA_STR + ac]);
                uint32_t a1 = __float_as_uint(Ab[(ar + 8) * QA_STR + ac]);
                uint32_t a2 = __float_as_uint(Ab[ar * QA_STR + ac + 4]);
                uint32_t a3 = __float_as_uint(Ab[(ar + 8) * QA_STR + ac + 4]);
                const int br = kk + (lane & 3);
                const int bc = lane >> 2;
                #pragma unroll
                for (int n = 0; n < 16; n++) {
                    uint32_t b0 = __float_as_uint(Wb[br * 136 + n * 8 + bc]);
                    uint32_t b1 = __float_as_uint(Wb[(br + 4) * 136 + n * 8 + bc]);
                    mma_tf32(acc[n], a0, a1, a2, a3, b0, b1);
                }
            }
            __syncthreads();
        }

        const int r  = r0 + ar;
        const int cb = 2 * (lane & 3);
        bf16* C = op[w];
        const float* bias = bp[w];
        #pragma unroll
        for (int n = 0; n < 16; n++) {
            const int col = n * 8 + cb;
            float2 bb = *(const float2*)(bias + col);
            if (r < M)     store2(C, (size_t)r * 128 + col,       acc[n][0] + bb.x, acc[n][1] + bb.y);
            if (r + 8 < M) store2(C, (size_t)(r + 8) * 128 + col, acc[n][2] + bb.x, acc[n][3] + bb.y);
        }
    }
}

// ============ single-weight GEMM (Wo / W1 / W2) ============
#define A_STG (128 * 36)
#define W_STG (32 * 136)
#define GEMM_SMEM ((2 * A_STG + 2 * W_STG) * sizeof(float))

template<int EPI, typename OutT>
__global__ __launch_bounds__(256) void gemm_tc_kernel(const float* __restrict__ A,
                                                      const float* __restrict__ W,
                                                      const float* __restrict__ bias,
                                                      const float* __restrict__ R,
                                                      OutT* __restrict__ C, int M)
{
    extern __shared__ float smem[];
    float* As = smem;
    float* Ws = smem + 2 * A_STG;

    const int tid  = threadIdx.x;
    const int warp = tid >> 5;
    const int lane = tid & 31;
    const int r0   = blockIdx.x * 128;
    const uint32_t smem_base = (uint32_t)__cvta_generic_to_shared(smem);

    float acc[16][4];
    #pragma unroll
    for (int n = 0; n < 16; n++)
        #pragma unroll
        for (int j = 0; j < 4; j++) acc[n][j] = 0.0f;

    auto stage = [&](int s, int k0) {
        #pragma unroll
        for (int i = 0; i < 4; i++) {
            int lin = tid + i * 256;
            int r   = lin >> 3;
            int c4  = lin & 7;
            uint32_t dst = smem_base + (uint32_t)((s * A_STG + r * 36 + c4 * 4) * 4);
            cp16(dst, A + (size_t)(r0 + r) * 128 + k0 + c4 * 4, r0 + r < M);
        }
        #pragma unroll
        for (int i = 0; i < 4; i++) {
            int lin = tid + i * 256;
            int kr  = lin >> 5;
            int c4  = lin & 31;
            uint32_t dst = smem_base + (uint32_t)((2 * A_STG + s * W_STG + kr * 136 + c4 * 4) * 4);
            cp16(dst, W + (size_t)(k0 + kr) * 128 + c4 * 4, true);
        }
    };

    stage(0, 0);
    cp_commit();

    #pragma unroll
    for (int kc = 0; kc < 4; kc++) {
        if (kc < 3) stage((kc + 1) & 1, (kc + 1) * 32);
        cp_commit();
        cp_wait1();
        __syncthreads();

        const float* Ab = As + (kc & 1) * A_STG;
        const float* Wb = Ws + (kc & 1) * W_STG;
        const int ar = warp * 16 + (lane >> 2);
        #pragma unroll
        for (int kk = 0; kk < 32; kk += 8) {
            const int ac = kk + (lane & 3);
            uint32_t a0 = __float_as_uint(Ab[ar * 36 + ac]);
            uint32_t a1 = __float_as_uint(Ab[(ar + 8) * 36 + ac]);
            uint32_t a2 = __float_as_uint(Ab[ar * 36 + ac + 4]);
            uint32_t a3 = __float_as_uint(Ab[(ar + 8) * 36 + ac + 4]);
            const int br = kk + (lane & 3);
            const int bc = lane >> 2;
            #pragma unroll
            for (int n = 0; n < 16; n++) {
                uint32_t b0 = __float_as_uint(Wb[br * 136 + n * 8 + bc]);
                uint32_t b1 = __float_as_uint(Wb[(br + 4) * 136 + n * 8 + bc]);
                mma_tf32(acc[n], a0, a1, a2, a3, b0, b1);
            }
        }
        __syncthreads();
    }

    const int r  = r0 + warp * 16 + (lane >> 2);
    const int cb = 2 * (lane & 3);
    #pragma unroll
    for (int n = 0; n < 16; n++) {
        const int col = n * 8 + cb;
        float2 bb = *(const float2*)(bias + col);
        float v0 = acc[n][0] + bb.x, v1 = acc[n][1] + bb.y;
        float v2 = acc[n][2] + bb.x, v3 = acc[n][3] + bb.y;
        if (EPI == EPI_GELU) {
            v0 = gelu_exact(v0); v1 = gelu_exact(v1);
            v2 = gelu_exact(v2); v3 = gelu_exact(v3);
        }
        if (r < M) {
            float a0 = v0, a1 = v1;
            if (EPI == EPI_RES) {
                float2 rv = *(const float2*)(R + (size_t)r * 128 + col);
                a0 += rv.x; a1 += rv.y;
            }
            store2(C, (size_t)r * 128 + col, a0, a1);
        }
        if (r + 8 < M) {
            float a2 = v2, a3 = v3;
            if (EPI == EPI_RES) {
                float2 rv = *(const float2*)(R + (size_t)(r + 8) * 128 + col);
                a2 += rv.x; a3 += rv.y;
            }
            store2(C, (size_t)(r + 8) * 128 + col, a2, a3);
        }
    }
}

// ---------------- fused edge pass (vector red) ----------------
__device__ __forceinline__ void red_v4(float* ptr, float a, float b, float c, float d)
{
    asm volatile("red.global.add.v4.f32 [%0], {%1, %2, %3, %4};"
                 :: "l"(ptr), "f"(a), "f"(b), "f"(c), "f"(d) : "memory");
}

__global__ __launch_bounds__(256) void edge_attn_kernel(const bf16* __restrict__ Q,
                                                        const bf16* __restrict__ K,
                                                        const bf16* __restrict__ V,
                                                        const int* __restrict__ row,
                                                        const int* __restrict__ col,
                                                        const float* __restrict__ bias,
                                                        float* __restrict__ num,
                                                        float* __restrict__ z,
                                                        int qoff, int koff, int ooff, int ne)
{
    int e = blockIdx.x * 8 + (threadIdx.x >> 5);
    if (e >= ne) return;
    int lane = threadIdx.x & 31;
    int h = lane >> 2;
    int r = row[e], c = col[e];

    uint2 qraw = *((const uint2*)(Q + (size_t)(r + qoff) * HID) + lane);
    uint2 kraw = *((const uint2*)(K + (size_t)(c + koff) * HID) + lane);
    float2 qa = __bfloat1622float2(*(bf162*)&qraw.x);
    float2 qb = __bfloat1622float2(*(bf162*)&qraw.y);
    float2 ka = __bfloat1622float2(*(bf162*)&kraw.x);
    float2 kb = __bfloat1622float2(*(bf162*)&kraw.y);
    float d = qa.x * ka.x + qa.y * ka.y + qb.x * kb.x + qb.y * kb.y;
    d += __shfl_xor_sync(0xffffffffu, d, 1);
    d += __shfl_xor_sync(0xffffffffu, d, 2);

    float sc = d * SCALE + __ldg(&bias[(size_t)e * NHD + h]);
    float ex = __expf(sc);
    if ((lane & 3) == 0) atomicAdd(&z[(size_t)r * NHD + h], ex);

    uint2 vraw = *((const uint2*)(V + (size_t)(c + koff) * HID) + lane);
    float2 va = __bfloat1622float2(*(bf162*)&vraw.x);
    float2 vb = __bfloat1622float2(*(bf162*)&vraw.y);
    red_v4(num + (size_t)(r + ooff) * HID + lane * 4,
           ex * va.x, ex * va.y, ex * vb.x, ex * vb.y);
}

// ---------------- normalize ----------------
__global__ __launch_bounds__(256) void norm_kernel(float* __restrict__ o,
                                                   const float* __restrict__ z, int n)
{
    int row = blockIdx.x * 8 + (threadIdx.x >> 5);
    if (row >= n) return;
    int lane = threadIdx.x & 31;
    float rz = 1.0f / (z[(size_t)row * NHD + (lane >> 2)] + 1e-16f);
    float4* p = (float4*)(o + (size_t)row * HID) + lane;
    float4 v = *p;
    v.x *= rz; v.y *= rz; v.z *= rz; v.w *= rz;
    *p = v;
}

// ---------------- host ----------------
extern "C" void kernel_launch(void* const* d_in, const int* in_sizes, int n_in,
                              void* d_out, int out_size)
{
    const float* x_all    = (const float*)d_in[0];
    const float* bias_c2t = (const float*)d_in[1];
    const float* bias_t2c = (const float*)d_in[2];
    const int*   c2t_row  = (const int*)d_in[3];
    const int*   c2t_col  = (const int*)d_in[4];
    const int*   t2c_row  = (const int*)d_in[5];
    const int*   t2c_col  = (const int*)d_in[6];
    const float* ln1_g    = (const float*)d_in[7];
    const float* ln1_b    = (const float*)d_in[8];
    const float* Wq = (const float*)d_in[9];   const float* bq = (const float*)d_in[10];
    const float* Wk = (const float*)d_in[11];  const float* bk = (const float*)d_in[12];
    const float* Wv = (const float*)d_in[13];  const float* bv = (const float*)d_in[14];
    const float* Wo = (const float*)d_in[15];  const float* bo = (const float*)d_in[16];
    const float* ln2_g = (const float*)d_in[17];
    const float* ln2_b = (const float*)d_in[18];
    const float* W1 = (const float*)d_in[19];  const float* b1 = (const float*)d_in[20];
    const float* W2 = (const float*)d_in[21];  const float* b2 = (const float*)d_in[22];
    float* out = (float*)d_out;

    float *y, *o, *x, *h, *z1, *z2;
    bf16 *qb, *kb, *vb;
    cudaGetSymbolAddress((void**)&y,  g_y);
    cudaGetSymbolAddress((void**)&qb, g_qb);
    cudaGetSymbolAddress((void**)&kb, g_kb);
    cudaGetSymbolAddress((void**)&vb, g_vb);
    cudaGetSymbolAddress((void**)&o,  g_o);
    cudaGetSymbolAddress((void**)&x,  g_x);
    cudaGetSymbolAddress((void**)&h,  g_h);
    cudaGetSymbolAddress((void**)&z1, g_z1);
    cudaGetSymbolAddress((void**)&z2, g_z2);

    cudaFuncSetAttribute(qkv_kernel,
                         cudaFuncAttributeMaxDynamicSharedMemorySize, QKV_SMEM);
    cudaFuncSetAttribute(gemm_tc_kernel<EPI_RES, float>,
                         cudaFuncAttributeMaxDynamicSharedMemorySize, GEMM_SMEM);
    cudaFuncSetAttribute(gemm_tc_kernel<EPI_GELU, float>,
                         cudaFuncAttributeMaxDynamicSharedMemorySize, GEMM_SMEM);

    const int lnGrid   = (NALL + 7) / 8;
    const int gemmGrid = (NALL + 127) / 128;
    const int edgeGrid = (EDG + 7) / 8;

    ln_kernel<<<lnGrid, 256>>>(x_all, ln1_g, ln1_b, y, NALL);

    qkv_kernel<<<gemmGrid, 256, QKV_SMEM>>>(y, Wq, Wk, Wv, bq, bk, bv, qb, kb, vb, NALL);

    cudaMemsetAsync(z1, 0, (size_t)NT * NHD * sizeof(float), 0);
    cudaMemsetAsync(z2, 0, (size_t)NC * NHD * sizeof(float), 0);
    cudaMemsetAsync(o,  0, (size_t)NALL * HID * sizeof(float), 0);

    edge_attn_kernel<<<edgeGrid, 256>>>(qb, kb, vb, c2t_row, c2t_col, bias_c2t,
                                        o, z1, 0, NT, NC, EDG);
    edge_attn_kernel<<<edgeGrid, 256>>>(qb, kb, vb, t2c_row, t2c_col, bias_t2c,
                                        o, z2, NT, 0, 0, EDG);

    norm_kernel<<<(NC + 7) / 8, 256>>>(o, z2, NC);
    norm_kernel<<<(NT + 7) / 8, 256>>>(o + (size_t)NC * HID, z1, NT);

    gemm_tc_kernel<EPI_RES, float><<<gemmGrid, 256, GEMM_SMEM>>>(o, Wo, bo, x_all, x, NALL);

    ln_kernel<<<lnGrid, 256>>>(x, ln2_g, ln2_b, h, NALL);

    gemm_tc_kernel<EPI_GELU, float><<<gemmGrid, 256, GEMM_SMEM>>>(h, W1, b1, nullptr, y, NALL);

    gemm_tc_kernel<EPI_RES, float><<<gemmGrid, 256, GEMM_SMEM>>>(y, W2, b2, x, out, NALL);
}

// round 6
// speedup vs baseline: 2.2601x; 1.0509x over previous
#include <cuda_runtime.h>
#include <cuda_bf16.h>
#include <math.h>
#include <stdint.h>

#define NT 20000
#define NC 80000
#define NALL 100000
#define HID 128
#define NHD 8
#define EDG 500000
#define SCALE 0.25f

typedef __nv_bfloat16 bf16;
typedef __nv_bfloat162 bf162;

// ---------------- scratch ----------------
__device__ float g_y [(size_t)NALL * HID];   // gelu intermediate
__device__ bf16  g_qb[(size_t)NALL * HID];
__device__ bf16  g_kb[(size_t)NALL * HID];
__device__ bf16  g_vb[(size_t)NALL * HID];
__device__ float g_o [(size_t)NALL * HID];
__device__ float g_x [(size_t)NALL * HID];
__device__ float g_h [(size_t)NALL * HID];
// CSR build scratch (shared between the two directions, used sequentially)
__device__ int g_cnt  [NC];
__device__ int g_start[NC];
__device__ int g_fill [NC];
__device__ int g_sorted[EDG];
__device__ int g_bsum [128];

// ---------------- LayerNorm (standalone, used for LN2) ----------------
__global__ __launch_bounds__(256) void ln_kernel(const float* __restrict__ x,
                                                 const float* __restrict__ g,
                                                 const float* __restrict__ b,
                                                 float* __restrict__ y, int n)
{
    int row = blockIdx.x * 8 + (threadIdx.x >> 5);
    if (row >= n) return;
    int lane = threadIdx.x & 31;
    const float4 v = ((const float4*)(x + (size_t)row * HID))[lane];
    float s  = v.x + v.y + v.z + v.w;
    float ss = v.x * v.x + v.y * v.y + v.z * v.z + v.w * v.w;
    #pragma unroll
    for (int off = 16; off > 0; off >>= 1) {
        s  += __shfl_xor_sync(0xffffffffu, s,  off);
        ss += __shfl_xor_sync(0xffffffffu, ss, off);
    }
    float mean = s * (1.0f / HID);
    float var  = ss * (1.0f / HID) - mean * mean;
    float rstd = rsqrtf(var + 1e-5f);
    const float4 gv = ((const float4*)g)[lane];
    const float4 bv = ((const float4*)b)[lane];
    float4 o;
    o.x = (v.x - mean) * rstd * gv.x + bv.x;
    o.y = (v.y - mean) * rstd * gv.y + bv.y;
    o.z = (v.z - mean) * rstd * gv.z + bv.z;
    o.w = (v.w - mean) * rstd * gv.w + bv.w;
    ((float4*)(y + (size_t)row * HID))[lane] = o;
}

// ---------------- GEMM helpers ----------------
__device__ __forceinline__ float gelu_exact(float x)
{
    return 0.5f * x * (1.0f + erff(x * 0.70710678118654752f));
}

__device__ __forceinline__ void mma_tf32(float c[4], uint32_t a0, uint32_t a1,
                                         uint32_t a2, uint32_t a3,
                                         uint32_t b0, uint32_t b1)
{
    asm volatile(
        "mma.sync.aligned.m16n8k8.row.col.f32.tf32.tf32.f32 "
        "{%0,%1,%2,%3}, {%4,%5,%6,%7}, {%8,%9}, {%0,%1,%2,%3};"
        : "+f"(c[0]), "+f"(c[1]), "+f"(c[2]), "+f"(c[3])
        : "r"(a0), "r"(a1), "r"(a2), "r"(a3), "r"(b0), "r"(b1));
}

__device__ __forceinline__ void cp16(uint32_t dst, const void* src, bool pred)
{
    asm volatile("cp.async.cg.shared.global [%0], [%1], 16, %2;\n"
                 :: "r"(dst), "l"(src), "r"(pred ? 16 : 0));
}
__device__ __forceinline__ void cp_commit() { asm volatile("cp.async.commit_group;\n"); }
__device__ __forceinline__ void cp_wait1()  { asm volatile("cp.async.wait_group 1;\n"); }
__device__ __forceinline__ void cp_wait0()  { asm volatile("cp.async.wait_group 0;\n"); }

__device__ __forceinline__ void store2(float* C, size_t idx, float a, float b)
{
    *(float2*)(C + idx) = make_float2(a, b);
}
__device__ __forceinline__ void store2(bf16* C, size_t idx, float a, float b)
{
    *(bf162*)(C + idx) = __floats2bfloat162_rn(a, b);
}

#define EPI_NONE 0
#define EPI_RES  1
#define EPI_GELU 2

// ============ fused LN1 + QKV GEMM: A staged once, LN in smem, 3 weights ============
#define QA_STR 132
#define QA_SZ  (128 * QA_STR)
#define QW_STG (32 * 136)
#define QKV_SMEM ((QA_SZ + 2 * QW_STG) * sizeof(float))

__global__ __launch_bounds__(256) void qkv_kernel(const float* __restrict__ A,
                                                  const float* __restrict__ lng,
                                                  const float* __restrict__ lnb,
                                                  const float* __restrict__ Wq,
                                                  const float* __restrict__ Wk,
                                                  const float* __restrict__ Wv,
                                                  const float* __restrict__ bq,
                                                  const float* __restrict__ bk,
                                                  const float* __restrict__ bv,
                                                  bf16* __restrict__ Oq,
                                                  bf16* __restrict__ Ok,
                                                  bf16* __restrict__ Ov, int M)
{
    extern __shared__ float smem[];
    float* As = smem;                 // [128][132]
    float* Ws = smem + QA_SZ;         // [2][32][136]

    const float* Wp[3] = {Wq, Wk, Wv};
    const float* bp[3] = {bq, bk, bv};
    bf16*        op[3] = {Oq, Ok, Ov};

    const int tid  = threadIdx.x;
    const int warp = tid >> 5;
    const int lane = tid & 31;
    const int r0   = blockIdx.x * 128;
    const uint32_t smem_base = (uint32_t)__cvta_generic_to_shared(smem);

    auto stageW = [&](int s, const float* W, int k0) {
        #pragma unroll
        for (int i = 0; i < 4; i++) {
            int lin = tid + i * 256;
            int kr  = lin >> 5;
            int c4  = lin & 31;
            uint32_t dst = smem_base + (uint32_t)((QA_SZ + s * QW_STG + kr * 136 + c4 * 4) * 4);
            cp16(dst, W + (size_t)(k0 + kr) * 128 + c4 * 4, true);
        }
    };

    // stage full raw A (128x128) + W[0] chunk 0
    #pragma unroll
    for (int i = 0; i < 16; i++) {
        int lin = tid + i * 256;
        int r   = lin >> 5;
        int c4  = lin & 31;
        uint32_t dst = smem_base + (uint32_t)((r * QA_STR + c4 * 4) * 4);
        cp16(dst, A + (size_t)(r0 + r) * 128 + c4 * 4, r0 + r < M);
    }
    stageW(0, Wq, 0);
    cp_commit();
    cp_wait0();
    __syncthreads();

    // fused LN over the staged A tile: 2 threads per row
    {
        int r = tid >> 1, half = tid & 1;
        float* rowp = As + r * QA_STR + half * 64;
        float s = 0.f, ss = 0.f;
        #pragma unroll
        for (int j = 0; j < 32; j++) {
            float2 v = *(float2*)(rowp + j * 2);
            s += v.x + v.y; ss += v.x * v.x + v.y * v.y;
        }
        s  += __shfl_xor_sync(0xffffffffu, s, 1);
        ss += __shfl_xor_sync(0xffffffffu, ss, 1);
        float mean = s * (1.0f / HID);
        float var  = ss * (1.0f / HID) - mean * mean;
        float rstd = rsqrtf(var + 1e-5f);
        const float* gp = lng + half * 64;
        const float* bb = lnb + half * 64;
        #pragma unroll
        for (int j = 0; j < 32; j++) {
            float2 v  = *(float2*)(rowp + j * 2);
            float2 gv = *(const float2*)(gp + j * 2);
            float2 bv = *(const float2*)(bb + j * 2);
            v.x = (v.x - mean) * rstd * gv.x + bv.x;
            v.y = (v.y - mean) * rstd * gv.y + bv.y;
            *(float2*)(rowp + j * 2) = v;
        }
    }
    __syncthreads();

    const int ar = warp * 16 + (lane >> 2);
    #pragma unroll
    for (int w = 0; w < 3; w++) {
        float acc[16][4];
        #pragma unroll
        for (int n = 0; n < 16; n++)
            #pragma unroll
            for (int j = 0; j < 4; j++) acc[n][j] = 0.0f;

        #pragma unroll
        for (int kc = 0; kc < 4; kc++) {
            int t = w * 4 + kc;
            if (t < 11) {
                int nt = t + 1;
                stageW(nt & 1, Wp[nt >> 2], (nt & 3) * 32);
            }
            cp_commit();
            cp_wait1();
            __syncthreads();

            const float* Ab = As + kc * 32;
            const float* Wb = Ws + (t & 1) * QW_STG;
            #pragma unroll
            for (int kk = 0; kk < 32; kk += 8) {
                const int ac = kk + (lane & 3);
                uint32_t a0 = __float_as_uint(Ab[ar * QA_STR + ac]);
                uint32_t a1 = __float_as_uint(Ab[(ar + 8) * QA_STR + ac]);
                uint32_t a2 = __float_as_uint(Ab[ar * QA_STR + ac + 4]);
                uint32_t a3 = __float_as_uint(Ab[(ar + 8) * QA_STR + ac + 4]);
                const int br = kk + (lane & 3);
                const int bc = lane >> 2;
                #pragma unroll
                for (int n = 0; n < 16; n++) {
                    uint32_t b0 = __float_as_uint(Wb[br * 136 + n * 8 + bc]);
                    uint32_t b1 = __float_as_uint(Wb[(br + 4) * 136 + n * 8 + bc]);
                    mma_tf32(acc[n], a0, a1, a2, a3, b0, b1);
                }
            }
            __syncthreads();
        }

        const int r  = r0 + ar;
        const int cb = 2 * (lane & 3);
        bf16* C = op[w];
        const float* bias = bp[w];
        #pragma unroll
        for (int n = 0; n < 16; n++) {
            const int col = n * 8 + cb;
            float2 bb = *(const float2*)(bias + col);
            if (r < M)     store2(C, (size_t)r * 128 + col,       acc[n][0] + bb.x, acc[n][1] + bb.y);
            if (r + 8 < M) store2(C, (size_t)(r + 8) * 128 + col, acc[n][2] + bb.x, acc[n][3] + bb.y);
        }
    }
}

// ============ single-weight GEMM (Wo / W1 / W2) ============
#define A_STG (128 * 36)
#define W_STG (32 * 136)
#define GEMM_SMEM ((2 * A_STG + 2 * W_STG) * sizeof(float))

template<int EPI, typename OutT>
__global__ __launch_bounds__(256) void gemm_tc_kernel(const float* __restrict__ A,
                                                      const float* __restrict__ W,
                                                      const float* __restrict__ bias,
                                                      const float* __restrict__ R,
                                                      OutT* __restrict__ C, int M)
{
    extern __shared__ float smem[];
    float* As = smem;
    float* Ws = smem + 2 * A_STG;

    const int tid  = threadIdx.x;
    const int warp = tid >> 5;
    const int lane = tid & 31;
    const int r0   = blockIdx.x * 128;
    const uint32_t smem_base = (uint32_t)__cvta_generic_to_shared(smem);

    float acc[16][4];
    #pragma unroll
    for (int n = 0; n < 16; n++)
        #pragma unroll
        for (int j = 0; j < 4; j++) acc[n][j] = 0.0f;

    auto stage = [&](int s, int k0) {
        #pragma unroll
        for (int i = 0; i < 4; i++) {
            int lin = tid + i * 256;
            int r   = lin >> 3;
            int c4  = lin & 7;
            uint32_t dst = smem_base + (uint32_t)((s * A_STG + r * 36 + c4 * 4) * 4);
            cp16(dst, A + (size_t)(r0 + r) * 128 + k0 + c4 * 4, r0 + r < M);
        }
        #pragma unroll
        for (int i = 0; i < 4; i++) {
            int lin = tid + i * 256;
            int kr  = lin >> 5;
            int c4  = lin & 31;
            uint32_t dst = smem_base + (uint32_t)((2 * A_STG + s * W_STG + kr * 136 + c4 * 4) * 4);
            cp16(dst, W + (size_t)(k0 + kr) * 128 + c4 * 4, true);
        }
    };

    stage(0, 0);
    cp_commit();

    #pragma unroll
    for (int kc = 0; kc < 4; kc++) {
        if (kc < 3) stage((kc + 1) & 1, (kc + 1) * 32);
        cp_commit();
        cp_wait1();
        __syncthreads();

        const float* Ab = As + (kc & 1) * A_STG;
        const float* Wb = Ws + (kc & 1) * W_STG;
        const int ar = warp * 16 + (lane >> 2);
        #pragma unroll
        for (int kk = 0; kk < 32; kk += 8) {
            const int ac = kk + (lane & 3);
            uint32_t a0 = __float_as_uint(Ab[ar * 36 + ac]);
            uint32_t a1 = __float_as_uint(Ab[(ar + 8) * 36 + ac]);
            uint32_t a2 = __float_as_uint(Ab[ar * 36 + ac + 4]);
            uint32_t a3 = __float_as_uint(Ab[(ar + 8) * 36 + ac + 4]);
            const int br = kk + (lane & 3);
            const int bc = lane >> 2;
            #pragma unroll
            for (int n = 0; n < 16; n++) {
                uint32_t b0 = __float_as_uint(Wb[br * 136 + n * 8 + bc]);
                uint32_t b1 = __float_as_uint(Wb[(br + 4) * 136 + n * 8 + bc]);
                mma_tf32(acc[n], a0, a1, a2, a3, b0, b1);
            }
        }
        __syncthreads();
    }

    const int r  = r0 + warp * 16 + (lane >> 2);
    const int cb = 2 * (lane & 3);
    #pragma unroll
    for (int n = 0; n < 16; n++) {
        const int col = n * 8 + cb;
        float2 bb = *(const float2*)(bias + col);
        float v0 = acc[n][0] + bb.x, v1 = acc[n][1] + bb.y;
        float v2 = acc[n][2] + bb.x, v3 = acc[n][3] + bb.y;
        if (EPI == EPI_GELU) {
            v0 = gelu_exact(v0); v1 = gelu_exact(v1);
            v2 = gelu_exact(v2); v3 = gelu_exact(v3);
        }
        if (r < M) {
            float a0 = v0, a1 = v1;
            if (EPI == EPI_RES) {
                float2 rv = *(const float2*)(R + (size_t)r * 128 + col);
                a0 += rv.x; a1 += rv.y;
            }
            store2(C, (size_t)r * 128 + col, a0, a1);
        }
        if (r + 8 < M) {
            float a2 = v2, a3 = v3;
            if (EPI == EPI_RES) {
                float2 rv = *(const float2*)(R + (size_t)(r + 8) * 128 + col);
                a2 += rv.x; a3 += rv.y;
            }
            store2(C, (size_t)(r + 8) * 128 + col, a2, a3);
        }
    }
}

// ================= CSR build =================
__global__ __launch_bounds__(256) void hist_kernel(const int* __restrict__ row,
                                                   int* __restrict__ cnt, int ne)
{
    int i = blockIdx.x * 256 + threadIdx.x;
    if (i < ne) atomicAdd(&cnt[row[i]], 1);
}

__global__ __launch_bounds__(256) void scan_reduce_kernel(const int* __restrict__ cnt,
                                                          int* __restrict__ bsum, int n)
{
    __shared__ int sm[256];
    int b = blockIdx.x, t = threadIdx.x;
    int base = b * 1024 + t * 4;
    int s = 0;
    #pragma unroll
    for (int j = 0; j < 4; j++)
        if (base + j < n) s += cnt[base + j];
    sm[t] = s;
    __syncthreads();
    for (int off = 128; off > 0; off >>= 1) {
        if (t < off) sm[t] += sm[t + off];
        __syncthreads();
    }
    if (t == 0) bsum[b] = sm[0];
}

__global__ void scan_bsum_kernel(int* __restrict__ bsum, int nb)
{
    if (threadIdx.x == 0) {
        int acc = 0;
        for (int i = 0; i < nb; i++) { int v = bsum[i]; bsum[i] = acc; acc += v; }
    }
}

__global__ __launch_bounds__(256) void scan_final_kernel(const int* __restrict__ cnt,
                                                         const int* __restrict__ bsum,
                                                         int* __restrict__ start,
                                                         int* __restrict__ fill, int n)
{
    int b = blockIdx.x, t = threadIdx.x;
    int lane = t & 31, w = t >> 5;
    int base = b * 1024 + t * 4;
    int v[4], s = 0;
    #pragma unroll
    for (int j = 0; j < 4; j++) {
        v[j] = (base + j < n) ? cnt[base + j] : 0;
        s += v[j];
    }
    int incl = s;
    #pragma unroll
    for (int off = 1; off < 32; off <<= 1) {
        int x = __shfl_up_sync(0xffffffffu, incl, off);
        if (lane >= off) incl += x;
    }
    __shared__ int wtot[8], woff[8];
    if (lane == 31) wtot[w] = incl;
    __syncthreads();
    if (t == 0) {
        int a = 0;
        for (int i = 0; i < 8; i++) { woff[i] = a; a += wtot[i]; }
    }
    __syncthreads();
    int off = bsum[b] + woff[w] + incl - s;
    #pragma unroll
    for (int j = 0; j < 4; j++) {
        if (base + j < n) { start[base + j] = off; fill[base + j] = off; }
        off += v[j];
    }
}

__global__ __launch_bounds__(256) void scatter_kernel(const int* __restrict__ row,
                                                      int* __restrict__ fill,
                                                      int* __restrict__ sorted, int ne)
{
    int i = blockIdx.x * 256 + threadIdx.x;
    if (i < ne) {
        int p = atomicAdd(&fill[row[i]], 1);
        sorted[p] = i;
    }
}

// ============ CSR edge aggregate: warp per destination row, no atomics ============
__global__ __launch_bounds__(256) void edge_agg_kernel(const bf16* __restrict__ Q,
                                                       const bf16* __restrict__ K,
                                                       const bf16* __restrict__ V,
                                                       const int* __restrict__ col,
                                                       const float* __restrict__ bias,
                                                       const int* __restrict__ start,
                                                       const int* __restrict__ cnt,
                                                       const int* __restrict__ sorted,
                                                       float* __restrict__ O,
                                                       int qoff, int koff, int ooff, int nrows)
{
    int r = blockIdx.x * 8 + (threadIdx.x >> 5);
    if (r >= nrows) return;
    int lane = threadIdx.x & 31;
    int h = lane >> 2;

    uint2 qraw = *((const uint2*)(Q + (size_t)(r + qoff) * HID) + lane);
    float2 qa = __bfloat1622float2(*(bf162*)&qraw.x);
    float2 qb = __bfloat1622float2(*(bf162*)&qraw.y);

    float a0 = 0.f, a1 = 0.f, a2 = 0.f, a3 = 0.f, z = 0.f;

    int s = start[r];
    int e_end = s + cnt[r];
    int e_nxt = 0, c_nxt = 0;
    if (s < e_end) {
        e_nxt = __ldg(&sorted[s]);
        c_nxt = __ldg(&col[e_nxt]);
    }
    for (int i = s; i < e_end; i++) {
        int e = e_nxt, c = c_nxt;
        if (i + 1 < e_end) {
            e_nxt = __ldg(&sorted[i + 1]);
            c_nxt = __ldg(&col[e_nxt]);
        }
        uint2 kraw = *((const uint2*)(K + (size_t)(c + koff) * HID) + lane);
        uint2 vraw = *((const uint2*)(V + (size_t)(c + koff) * HID) + lane);
        float2 ka = __bfloat1622float2(*(bf162*)&kraw.x);
        float2 kb = __bfloat1622float2(*(bf162*)&kraw.y);
        float d = qa.x * ka.x + qa.y * ka.y + qb.x * kb.x + qb.y * kb.y;
        d += __shfl_xor_sync(0xffffffffu, d, 1);
        d += __shfl_xor_sync(0xffffffffu, d, 2);
        float sc = d * SCALE + __ldg(&bias[(size_t)e * NHD + h]);
        float ex = __expf(sc);
        z += ex;
        float2 va = __bfloat1622float2(*(bf162*)&vraw.x);
        float2 vb = __bfloat1622float2(*(bf162*)&vraw.y);
        a0 += ex * va.x; a1 += ex * va.y;
        a2 += ex * vb.x; a3 += ex * vb.y;
    }

    float rz = 1.0f / (z + 1e-16f);
    *(float4*)(O + (size_t)(r + ooff) * HID + lane * 4) =
        make_float4(a0 * rz, a1 * rz, a2 * rz, a3 * rz);
}

// ---------------- host ----------------
extern "C" void kernel_launch(void* const* d_in, const int* in_sizes, int n_in,
                              void* d_out, int out_size)
{
    const float* x_all    = (const float*)d_in[0];
    const float* bias_c2t = (const float*)d_in[1];
    const float* bias_t2c = (const float*)d_in[2];
    const int*   c2t_row  = (const int*)d_in[3];
    const int*   c2t_col  = (const int*)d_in[4];
    const int*   t2c_row  = (const int*)d_in[5];
    const int*   t2c_col  = (const int*)d_in[6];
    const float* ln1_g    = (const float*)d_in[7];
    const float* ln1_b    = (const float*)d_in[8];
    const float* Wq = (const float*)d_in[9];   const float* bq = (const float*)d_in[10];
    const float* Wk = (const float*)d_in[11];  const float* bk = (const float*)d_in[12];
    const float* Wv = (const float*)d_in[13];  const float* bv = (const float*)d_in[14];
    const float* Wo = (const float*)d_in[15];  const float* bo = (const float*)d_in[16];
    const float* ln2_g = (const float*)d_in[17];
    const float* ln2_b = (const float*)d_in[18];
    const float* W1 = (const float*)d_in[19];  const float* b1 = (const float*)d_in[20];
    const float* W2 = (const float*)d_in[21];  const float* b2 = (const float*)d_in[22];
    float* out = (float*)d_out;

    float *y, *o, *x, *h;
    bf16 *qb, *kb, *vb;
    int *cnt, *start, *fill, *sorted, *bsum;
    cudaGetSymbolAddress((void**)&y,  g_y);
    cudaGetSymbolAddress((void**)&qb, g_qb);
    cudaGetSymbolAddress((void**)&kb, g_kb);
    cudaGetSymbolAddress((void**)&vb, g_vb);
    cudaGetSymbolAddress((void**)&o,  g_o);
    cudaGetSymbolAddress((void**)&x,  g_x);
    cudaGetSymbolAddress((void**)&h,  g_h);
    cudaGetSymbolAddress((void**)&cnt,    g_cnt);
    cudaGetSymbolAddress((void**)&start,  g_start);
    cudaGetSymbolAddress((void**)&fill,   g_fill);
    cudaGetSymbolAddress((void**)&sorted, g_sorted);
    cudaGetSymbolAddress((void**)&bsum,   g_bsum);

    cudaFuncSetAttribute(qkv_kernel,
                         cudaFuncAttributeMaxDynamicSharedMemorySize, QKV_SMEM);
    cudaFuncSetAttribute(gemm_tc_kernel<EPI_RES, float>,
                         cudaFuncAttributeMaxDynamicSharedMemorySize, GEMM_SMEM);
    cudaFuncSetAttribute(gemm_tc_kernel<EPI_GELU, float>,
                         cudaFuncAttributeMaxDynamicSharedMemorySize, GEMM_SMEM);

    const int lnGrid   = (NALL + 7) / 8;
    const int gemmGrid = (NALL + 127) / 128;
    const int eGrid    = (EDG + 255) / 256;

    // LN1 fused into QKV
    qkv_kernel<<<gemmGrid, 256, QKV_SMEM>>>(x_all, ln1_g, ln1_b, Wq, Wk, Wv,
                                            bq, bk, bv, qb, kb, vb, NALL);

    // ---- attn1 (ctx2tgt): rows in [0,NT), q off 0, k/v off NT, out off NC ----
    cudaMemsetAsync(cnt, 0, NT * sizeof(int), 0);
    hist_kernel<<<eGrid, 256>>>(c2t_row, cnt, EDG);
    {
        int nb = (NT + 1023) / 1024;
        scan_reduce_kernel<<<nb, 256>>>(cnt, bsum, NT);
        scan_bsum_kernel<<<1, 32>>>(bsum, nb);
        scan_final_kernel<<<nb, 256>>>(cnt, bsum, start, fill, NT);
    }
    scatter_kernel<<<eGrid, 256>>>(c2t_row, fill, sorted, EDG);
    edge_agg_kernel<<<(NT + 7) / 8, 256>>>(qb, kb, vb, c2t_col, bias_c2t,
                                           start, cnt, sorted, o, 0, NT, NC, NT);

    // ---- attn2 (tgt2cxt): rows in [0,NC), q off NT, k/v off 0, out off 0 ----
    cudaMemsetAsync(cnt, 0, NC * sizeof(int), 0);
    hist_kernel<<<eGrid, 256>>>(t2c_row, cnt, EDG);
    {
        int nb = (NC + 1023) / 1024;
        scan_reduce_kernel<<<nb, 256>>>(cnt, bsum, NC);
        scan_bsum_kernel<<<1, 32>>>(bsum, nb);
        scan_final_kernel<<<nb, 256>>>(cnt, bsum, start, fill, NC);
    }
    scatter_kernel<<<eGrid, 256>>>(t2c_row, fill, sorted, EDG);
    edge_agg_kernel<<<(NC + 7) / 8, 256>>>(qb, kb, vb, t2c_col, bias_t2c,
                                           start, cnt, sorted, o, NT, 0, 0, NC);

    // x = x_all + O @ Wo + bo
    gemm_tc_kernel<EPI_RES, float><<<gemmGrid, 256, GEMM_SMEM>>>(o, Wo, bo, x_all, x, NALL);

    // LN2
    ln_kernel<<<lnGrid, 256>>>(x, ln2_g, ln2_b, h, NALL);

    // y = gelu(h @ W1 + b1)
    gemm_tc_kernel<EPI_GELU, float><<<gemmGrid, 256, GEMM_SMEM>>>(h, W1, b1, nullptr, y, NALL);

    // out = x + y @ W2 + b2
    gemm_tc_kernel<EPI_RES, float><<<gemmGrid, 256, GEMM_SMEM>>>(y, W2, b2, x, out, NALL);
}

// round 7
// speedup vs baseline: 2.6958x; 1.1928x over previous
#include <cuda_runtime.h>
#include <cuda_bf16.h>
#include <math.h>
#include <stdint.h>

#define NT 20000
#define NC 80000
#define NALL 100000
#define HID 128
#define NHD 8
#define EDG 500000
#define SCALE 0.25f

typedef __nv_bfloat16 bf16;
typedef __nv_bfloat162 bf162;

// ---------------- scratch ----------------
__device__ bf16  g_qb[(size_t)NALL * HID];
__device__ bf16  g_kb[(size_t)NALL * HID];
__device__ bf16  g_vb[(size_t)NALL * HID];
__device__ float g_o [(size_t)NALL * HID];        // attention output (concat order)
__device__ int   g_cnt  [NALL];
__device__ int   g_start[NALL];
__device__ int   g_fill [NALL];
__device__ int   g_sorted[2 * EDG];
__device__ int   g_bsum [128];

// ---------------- GEMM helpers ----------------
__device__ __forceinline__ float gelu_exact(float x)
{
    return 0.5f * x * (1.0f + erff(x * 0.70710678118654752f));
}

__device__ __forceinline__ void mma_tf32(float c[4], uint32_t a0, uint32_t a1,
                                         uint32_t a2, uint32_t a3,
                                         uint32_t b0, uint32_t b1)
{
    asm volatile(
        "mma.sync.aligned.m16n8k8.row.col.f32.tf32.tf32.f32 "
        "{%0,%1,%2,%3}, {%4,%5,%6,%7}, {%8,%9}, {%0,%1,%2,%3};"
        : "+f"(c[0]), "+f"(c[1]), "+f"(c[2]), "+f"(c[3])
        : "r"(a0), "r"(a1), "r"(a2), "r"(a3), "r"(b0), "r"(b1));
}

__device__ __forceinline__ void cp16(uint32_t dst, const void* src, bool pred)
{
    asm volatile("cp.async.cg.shared.global [%0], [%1], 16, %2;\n"
                 :: "r"(dst), "l"(src), "r"(pred ? 16 : 0));
}
__device__ __forceinline__ void cp_commit() { asm volatile("cp.async.commit_group;\n"); }
__device__ __forceinline__ void cp_wait1()  { asm volatile("cp.async.wait_group 1;\n"); }
__device__ __forceinline__ void cp_wait0()  { asm volatile("cp.async.wait_group 0;\n"); }

__device__ __forceinline__ void store2(bf16* C, size_t idx, float a, float b)
{
    *(bf162*)(C + idx) = __floats2bfloat162_rn(a, b);
}

// shared chunk-MMA body. MODE 0: plain A. MODE 1: LN-on-the-fly A.
template<int MODE>
__device__ __forceinline__ void chunk_mma(float acc[16][4],
                                          const float* __restrict__ Ab, int astr,
                                          const float* __restrict__ Wb,
                                          int ar, int lane,
                                          const float* lng_s, const float* lnb_s,
                                          float m0, float rs0, float m1, float rs1)
{
    #pragma unroll
    for (int kk = 0; kk < 32; kk += 8) {
        const int ac = kk + (lane & 3);
        float ra0 = Ab[ar * astr + ac];
        float ra1 = Ab[(ar + 8) * astr + ac];
        float ra2 = Ab[ar * astr + ac + 4];
        float ra3 = Ab[(ar + 8) * astr + ac + 4];
        if (MODE == 1) {
            float g0 = lng_s[ac], b0 = lnb_s[ac];
            float g4 = lng_s[ac + 4], b4 = lnb_s[ac + 4];
            ra0 = (ra0 - m0) * rs0 * g0 + b0;
            ra1 = (ra1 - m1) * rs1 * g0 + b0;
            ra2 = (ra2 - m0) * rs0 * g4 + b4;
            ra3 = (ra3 - m1) * rs1 * g4 + b4;
        }
        uint32_t a0 = __float_as_uint(ra0), a1 = __float_as_uint(ra1);
        uint32_t a2 = __float_as_uint(ra2), a3 = __float_as_uint(ra3);
        const int br = kk + (lane & 3);
        const int bc = lane >> 2;
        #pragma unroll
        for (int n = 0; n < 16; n++) {
            uint32_t b0 = __float_as_uint(Wb[br * 136 + n * 8 + bc]);
            uint32_t b1 = __float_as_uint(Wb[(br + 4) * 136 + n * 8 + bc]);
            mma_tf32(acc[n], a0, a1, a2, a3, b0, b1);
        }
    }
}

// ============ fused LN1 + QKV GEMM ============
#define QA_STR 132
#define QA_SZ  (128 * QA_STR)
#define QW_STG (32 * 136)
#define QKV_SMEM ((QA_SZ + 2 * QW_STG) * sizeof(float))

__global__ __launch_bounds__(256) void qkv_kernel(const float* __restrict__ A,
                                                  const float* __restrict__ lng,
                                                  const float* __restrict__ lnb,
                                                  const float* __restrict__ Wq,
                                                  const float* __restrict__ Wk,
                                                  const float* __restrict__ Wv,
                                                  const float* __restrict__ bq,
                                                  const float* __restrict__ bk,
                                                  const float* __restrict__ bv,
                                                  bf16* __restrict__ Oq,
                                                  bf16* __restrict__ Ok,
                                                  bf16* __restrict__ Ov, int M)
{
    extern __shared__ float smem[];
    float* As = smem;                 // [128][132]
    float* Ws = smem + QA_SZ;         // [2][32][136]

    const float* Wp[3] = {Wq, Wk, Wv};
    const float* bp[3] = {bq, bk, bv};
    bf16*        op[3] = {Oq, Ok, Ov};

    const int tid  = threadIdx.x;
    const int warp = tid >> 5;
    const int lane = tid & 31;
    const int r0   = blockIdx.x * 128;
    const uint32_t smem_base = (uint32_t)__cvta_generic_to_shared(smem);

    auto stageW = [&](int s, const float* W, int k0) {
        #pragma unroll
        for (int i = 0; i < 4; i++) {
            int lin = tid + i * 256;
            int kr  = lin >> 5;
            int c4  = lin & 31;
            uint32_t dst = smem_base + (uint32_t)((QA_SZ + s * QW_STG + kr * 136 + c4 * 4) * 4);
            cp16(dst, W + (size_t)(k0 + kr) * 128 + c4 * 4, true);
        }
    };

    #pragma unroll
    for (int i = 0; i < 16; i++) {
        int lin = tid + i * 256;
        int r   = lin >> 5;
        int c4  = lin & 31;
        uint32_t dst = smem_base + (uint32_t)((r * QA_STR + c4 * 4) * 4);
        cp16(dst, A + (size_t)(r0 + r) * 128 + c4 * 4, r0 + r < M);
    }
    stageW(0, Wq, 0);
    cp_commit();
    cp_wait0();
    __syncthreads();

    // fused LN over staged A tile: 2 threads per row
    {
        int r = tid >> 1, half = tid & 1;
        float* rowp = As + r * QA_STR + half * 64;
        float s = 0.f, ss = 0.f;
        #pragma unroll
        for (int j = 0; j < 32; j++) {
            float2 v = *(float2*)(rowp + j * 2);
            s += v.x + v.y; ss += v.x * v.x + v.y * v.y;
        }
        s  += __shfl_xor_sync(0xffffffffu, s, 1);
        ss += __shfl_xor_sync(0xffffffffu, ss, 1);
        float mean = s * (1.0f / HID);
        float var  = ss * (1.0f / HID) - mean * mean;
        float rstd = rsqrtf(var + 1e-5f);
        const float* gp = lng + half * 64;
        const float* bb = lnb + half * 64;
        #pragma unroll
        for (int j = 0; j < 32; j++) {
            float2 v  = *(float2*)(rowp + j * 2);
            float2 gv = *(const float2*)(gp + j * 2);
            float2 bv = *(const float2*)(bb + j * 2);
            v.x = (v.x - mean) * rstd * gv.x + bv.x;
            v.y = (v.y - mean) * rstd * gv.y + bv.y;
            *(float2*)(rowp + j * 2) = v;
        }
    }
    __syncthreads();

    const int ar = warp * 16 + (lane >> 2);
    #pragma unroll
    for (int w = 0; w < 3; w++) {
        float acc[16][4];
        #pragma unroll
        for (int n = 0; n < 16; n++)
            #pragma unroll
            for (int j = 0; j < 4; j++) acc[n][j] = 0.0f;

        #pragma unroll
        for (int kc = 0; kc < 4; kc++) {
            int t = w * 4 + kc;
            if (t < 11) {
                int nt = t + 1;
                stageW(nt & 1, Wp[nt >> 2], (nt & 3) * 32);
            }
            cp_commit();
            cp_wait1();
            __syncthreads();
            chunk_mma<0>(acc, As + kc * 32, QA_STR, Ws + (t & 1) * QW_STG,
                         ar, lane, nullptr, nullptr, 0.f, 0.f, 0.f, 0.f);
            __syncthreads();
        }

        const int r  = r0 + ar;
        const int cb = 2 * (lane & 3);
        bf16* C = op[w];
        const float* bias = bp[w];
        #pragma unroll
        for (int n = 0; n < 16; n++) {
            const int col = n * 8 + cb;
            float2 bb = *(const float2*)(bias + col);
            if (r < M)     store2(C, (size_t)r * 128 + col,       acc[n][0] + bb.x, acc[n][1] + bb.y);
            if (r + 8 < M) store2(C, (size_t)(r + 8) * 128 + col, acc[n][2] + bb.x, acc[n][3] + bb.y);
        }
    }
}

// ============ tail mega-kernel: x=x_all+o@Wo+bo; LN2; @W1; gelu; @W2; +x ============
#define TL_STR 132
#define TL_SZ  (128 * TL_STR)
#define TAIL_SMEM ((2 * TL_SZ + 2 * QW_STG + 512) * sizeof(float))

__global__ __launch_bounds__(256) void tail_kernel(const float* __restrict__ Oin,
                                                   const float* __restrict__ x_all,
                                                   const float* __restrict__ Wo,
                                                   const float* __restrict__ bo,
                                                   const float* __restrict__ ln2g,
                                                   const float* __restrict__ ln2b,
                                                   const float* __restrict__ W1,
                                                   const float* __restrict__ b1,
                                                   const float* __restrict__ W2,
                                                   const float* __restrict__ b2,
                                                   float* __restrict__ out, int M)
{
    extern __shared__ float smem[];
    float* Xs     = smem;                         // o tile, then raw x
    float* Bs     = smem + TL_SZ;                 // gelu buffer
    float* Ws     = smem + 2 * TL_SZ;             // [2][32][136]
    float* sm_mean = Ws + 2 * QW_STG;             // [128]
    float* sm_rstd = sm_mean + 128;               // [128]
    float* lng_s   = sm_rstd + 128;               // [128]
    float* lnb_s   = lng_s + 128;                 // [128]

    const float* Wp[3] = {Wo, W1, W2};

    const int tid  = threadIdx.x;
    const int warp = tid >> 5;
    const int lane = tid & 31;
    const int r0   = blockIdx.x * 128;
    const uint32_t smem_base = (uint32_t)__cvta_generic_to_shared(smem);

    auto stageW = [&](int s, const float* W, int k0) {
        #pragma unroll
        for (int i = 0; i < 4; i++) {
            int lin = tid + i * 256;
            int kr  = lin >> 5;
            int c4  = lin & 31;
            uint32_t dst = smem_base + (uint32_t)((2 * TL_SZ + s * QW_STG + kr * 136 + c4 * 4) * 4);
            cp16(dst, W + (size_t)(k0 + kr) * 128 + c4 * 4, true);
        }
    };

    // stage o tile + Wo chunk 0; copy LN params
    #pragma unroll
    for (int i = 0; i < 16; i++) {
        int lin = tid + i * 256;
        int r   = lin >> 5;
        int c4  = lin & 31;
        uint32_t dst = smem_base + (uint32_t)((r * TL_STR + c4 * 4) * 4);
        cp16(dst, Oin + (size_t)(r0 + r) * 128 + c4 * 4, r0 + r < M);
    }
    stageW(0, Wo, 0);
    cp_commit();
    if (tid < 128) {
        lng_s[tid] = ln2g[tid];
        lnb_s[tid] = ln2b[tid];
    }

    const int ar = warp * 16 + (lane >> 2);
    const int cb = 2 * (lane & 3);
    const int rg = r0 + ar;                       // global row

    float acc[16][4];

    // ---- GEMM 1: o @ Wo ----
    #pragma unroll
    for (int n = 0; n < 16; n++)
        #pragma unroll
        for (int j = 0; j < 4; j++) acc[n][j] = 0.0f;
    #pragma unroll
    for (int kc = 0; kc < 4; kc++) {
        int t = kc;
        int nt = t + 1;
        stageW(nt & 1, Wp[nt >> 2], (nt & 3) * 32);
        cp_commit();
        cp_wait1();
        __syncthreads();
        chunk_mma<0>(acc, Xs + kc * 32, TL_STR, Ws + (t & 1) * QW_STG,
                     ar, lane, nullptr, nullptr, 0.f, 0.f, 0.f, 0.f);
        __syncthreads();
    }
    // epilogue 1: x = acc + bo + x_all -> Xs (o tile no longer needed)
    #pragma unroll
    for (int n = 0; n < 16; n++) {
        const int col = n * 8 + cb;
        float2 bb = *(const float2*)(bo + col);
        float2 xa = make_float2(0.f, 0.f), xb = make_float2(0.f, 0.f);
        if (rg < M)     xa = *(const float2*)(x_all + (size_t)rg * 128 + col);
        if (rg + 8 < M) xb = *(const float2*)(x_all + (size_t)(rg + 8) * 128 + col);
        Xs[ar * TL_STR + col]           = acc[n][0] + bb.x + xa.x;
        Xs[ar * TL_STR + col + 1]       = acc[n][1] + bb.y + xa.y;
        Xs[(ar + 8) * TL_STR + col]     = acc[n][2] + bb.x + xb.x;
        Xs[(ar + 8) * TL_STR + col + 1] = acc[n][3] + bb.y + xb.y;
    }
    __syncthreads();

    // LN2 stats: 2 threads per row
    {
        int r = tid >> 1, half = tid & 1;
        const float* rowp = Xs + r * TL_STR + half * 64;
        float s = 0.f, ss = 0.f;
        #pragma unroll
        for (int j = 0; j < 32; j++) {
            float2 v = *(const float2*)(rowp + j * 2);
            s += v.x + v.y; ss += v.x * v.x + v.y * v.y;
        }
        s  += __shfl_xor_sync(0xffffffffu, s, 1);
        ss += __shfl_xor_sync(0xffffffffu, ss, 1);
        if (half == 0) {
            float mean = s * (1.0f / HID);
            float var  = ss * (1.0f / HID) - mean * mean;
            sm_mean[r] = mean;
            sm_rstd[r] = rsqrtf(var + 1e-5f);
        }
    }
    __syncthreads();

    // ---- GEMM 2: LN2(x) @ W1 (normalize A on the fly) ----
    const float m0  = sm_mean[ar],     rs0 = sm_rstd[ar];
    const float m1  = sm_mean[ar + 8], rs1 = sm_rstd[ar + 8];
    #pragma unroll
    for (int n = 0; n < 16; n++)
        #pragma unroll
        for (int j = 0; j < 4; j++) acc[n][j] = 0.0f;
    #pragma unroll
    for (int kc = 0; kc < 4; kc++) {
        int t = 4 + kc;
        int nt = t + 1;
        stageW(nt & 1, Wp[nt >> 2], (nt & 3) * 32);
        cp_commit();
        cp_wait1();
        __syncthreads();
        chunk_mma<1>(acc, Xs + kc * 32, TL_STR, Ws + (t & 1) * QW_STG,
                     ar, lane, lng_s, lnb_s, m0, rs0, m1, rs1);
        __syncthreads();
    }
    // epilogue 2: gelu -> Bs
    #pragma unroll
    for (int n = 0; n < 16; n++) {
        const int col = n * 8 + cb;
        float2 bb = *(const float2*)(b1 + col);
        Bs[ar * TL_STR + col]           = gelu_exact(acc[n][0] + bb.x);
        Bs[ar * TL_STR + col + 1]       = gelu_exact(acc[n][1] + bb.y);
        Bs[(ar + 8) * TL_STR + col]     = gelu_exact(acc[n][2] + bb.x);
        Bs[(ar + 8) * TL_STR + col + 1] = gelu_exact(acc[n][3] + bb.y);
    }
    __syncthreads();

    // ---- GEMM 3: gelu @ W2 ----
    #pragma unroll
    for (int n = 0; n < 16; n++)
        #pragma unroll
        for (int j = 0; j < 4; j++) acc[n][j] = 0.0f;
    #pragma unroll
    for (int kc = 0; kc < 4; kc++) {
        int t = 8 + kc;
        if (t < 11) {
            int nt = t + 1;
            stageW(nt & 1, Wp[nt >> 2], (nt & 3) * 32);
        }
        cp_commit();
        cp_wait1();
        __syncthreads();
        chunk_mma<0>(acc, Bs + kc * 32, TL_STR, Ws + (t & 1) * QW_STG,
                     ar, lane, nullptr, nullptr, 0.f, 0.f, 0.f, 0.f);
        __syncthreads();
    }
    // epilogue 3: out = acc + b2 + x
    #pragma unroll
    for (int n = 0; n < 16; n++) {
        const int col = n * 8 + cb;
        float2 bb = *(const float2*)(b2 + col);
        if (rg < M) {
            float2 o;
            o.x = acc[n][0] + bb.x + Xs[ar * TL_STR + col];
            o.y = acc[n][1] + bb.y + Xs[ar * TL_STR + col + 1];
            *(float2*)(out + (size_t)rg * 128 + col) = o;
        }
        if (rg + 8 < M) {
            float2 o;
            o.x = acc[n][2] + bb.x + Xs[(ar + 8) * TL_STR + col];
            o.y = acc[n][3] + bb.y + Xs[(ar + 8) * TL_STR + col + 1];
            *(float2*)(out + (size_t)(rg + 8) * 128 + col) = o;
        }
    }
}

// ================= combined CSR build =================
__global__ __launch_bounds__(256) void hist_kernel(const int* __restrict__ row1,
                                                   const int* __restrict__ row2,
                                                   int* __restrict__ cnt)
{
    int i = blockIdx.x * 256 + threadIdx.x;
    if (i < EDG) {
        atomicAdd(&cnt[row1[i]], 1);
        atomicAdd(&cnt[NT + row2[i]], 1);
    }
}

__global__ __launch_bounds__(256) void scan_reduce_kernel(const int* __restrict__ cnt,
                                                          int* __restrict__ bsum, int n)
{
    __shared__ int sm[256];
    int b = blockIdx.x, t = threadIdx.x;
    int base = b * 1024 + t * 4;
    int s = 0;
    #pragma unroll
    for (int j = 0; j < 4; j++)
        if (base + j < n) s += cnt[base + j];
    sm[t] = s;
    __syncthreads();
    for (int off = 128; off > 0; off >>= 1) {
        if (t < off) sm[t] += sm[t + off];
        __syncthreads();
    }
    if (t == 0) bsum[b] = sm[0];
}

__global__ void scan_bsum_kernel(int* __restrict__ bsum, int nb)
{
    if (threadIdx.x == 0) {
        int acc = 0;
        for (int i = 0; i < nb; i++) { int v = bsum[i]; bsum[i] = acc; acc += v; }
    }
}

__global__ __launch_bounds__(256) void scan_final_kernel(const int* __restrict__ cnt,
                                                         const int* __restrict__ bsum,
                                                         int* __restrict__ start,
                                                         int* __restrict__ fill, int n)
{
    int b = blockIdx.x, t = threadIdx.x;
    int lane = t & 31, w = t >> 5;
    int base = b * 1024 + t * 4;
    int v[4], s = 0;
    #pragma unroll
    for (int j = 0; j < 4; j++) {
        v[j] = (base + j < n) ? cnt[base + j] : 0;
        s += v[j];
    }
    int incl = s;
    #pragma unroll
    for (int off = 1; off < 32; off <<= 1) {
        int x = __shfl_up_sync(0xffffffffu, incl, off);
        if (lane >= off) incl += x;
    }
    __shared__ int wtot[8], woff[8];
    if (lane == 31) wtot[w] = incl;
    __syncthreads();
    if (t == 0) {
        int a = 0;
        for (int i = 0; i < 8; i++) { woff[i] = a; a += wtot[i]; }
    }
    __syncthreads();
    int off = bsum[b] + woff[w] + incl - s;
    #pragma unroll
    for (int j = 0; j < 4; j++) {
        if (base + j < n) { start[base + j] = off; fill[base + j] = off; }
        off += v[j];
    }
}

__global__ __launch_bounds__(256) void scatter_kernel(const int* __restrict__ row1,
                                                      const int* __restrict__ row2,
                                                      int* __restrict__ fill,
                                                      int* __restrict__ sorted)
{
    int i = blockIdx.x * 256 + threadIdx.x;
    if (i < EDG) {
        int p1 = atomicAdd(&fill[row1[i]], 1);
        sorted[p1] = i;
        int p2 = atomicAdd(&fill[NT + row2[i]], 1);
        sorted[p2] = i;
    }
}

// ============ combined CSR edge aggregate: warp per destination row ============
__global__ __launch_bounds__(256) void edge_agg_kernel(const bf16* __restrict__ Q,
                                                       const bf16* __restrict__ K,
                                                       const bf16* __restrict__ V,
                                                       const int* __restrict__ col1,
                                                       const int* __restrict__ col2,
                                                       const float* __restrict__ bias1,
                                                       const float* __restrict__ bias2,
                                                       const int* __restrict__ start,
                                                       const int* __restrict__ cnt,
                                                       const int* __restrict__ sorted,
                                                       float* __restrict__ O)
{
    int r = blockIdx.x * 8 + (threadIdx.x >> 5);
    if (r >= NALL) return;
    int lane = threadIdx.x & 31;
    int h = lane >> 2;

    const bool dir1 = (r < NT);
    const int* col  = dir1 ? col1  : col2;
    const float* bias = dir1 ? bias1 : bias2;
    const int koff  = dir1 ? NT : 0;
    const int orow  = dir1 ? (NC + r) : (r - NT);

    uint2 qraw = *((const uint2*)(Q + (size_t)r * HID) + lane);
    float2 qa = __bfloat1622float2(*(bf162*)&qraw.x);
    float2 qb = __bfloat1622float2(*(bf162*)&qraw.y);

    float a0 = 0.f, a1 = 0.f, a2 = 0.f, a3 = 0.f, z = 0.f;

    int i = start[r];
    const int e_end = i + cnt[r];

    for (; i + 2 <= e_end; i += 2) {
        int e1 = __ldg(&sorted[i]);
        int e2 = __ldg(&sorted[i + 1]);
        int c1 = __ldg(&col[e1]);
        int c2 = __ldg(&col[e2]);
        uint2 k1 = *((const uint2*)(K + (size_t)(c1 + koff) * HID) + lane);
        uint2 v1 = *((const uint2*)(V + (size_t)(c1 + koff) * HID) + lane);
        uint2 k2 = *((const uint2*)(K + (size_t)(c2 + koff) * HID) + lane);
        uint2 v2 = *((const uint2*)(V + (size_t)(c2 + koff) * HID) + lane);
        float b1v = __ldg(&bias[(size_t)e1 * NHD + h]);
        float b2v = __ldg(&bias[(size_t)e2 * NHD + h]);

        float2 ka = __bfloat1622float2(*(bf162*)&k1.x);
        float2 kb = __bfloat1622float2(*(bf162*)&k1.y);
        float d1 = qa.x * ka.x + qa.y * ka.y + qb.x * kb.x + qb.y * kb.y;
        float2 kc = __bfloat1622float2(*(bf162*)&k2.x);
        float2 kd = __bfloat1622float2(*(bf162*)&k2.y);
        float d2 = qa.x * kc.x + qa.y * kc.y + qb.x * kd.x + qb.y * kd.y;
        d1 += __shfl_xor_sync(0xffffffffu, d1, 1);
        d2 += __shfl_xor_sync(0xffffffffu, d2, 1);
        d1 += __shfl_xor_sync(0xffffffffu, d1, 2);
        d2 += __shfl_xor_sync(0xffffffffu, d2, 2);

        float ex1 = __expf(d1 * SCALE + b1v);
        float ex2 = __expf(d2 * SCALE + b2v);
        z += ex1 + ex2;
        float2 va = __bfloat1622float2(*(bf162*)&v1.x);
        float2 vb = __bfloat1622float2(*(bf162*)&v1.y);
        float2 vc = __bfloat1622float2(*(bf162*)&v2.x);
        float2 vd = __bfloat1622float2(*(bf162*)&v2.y);
        a0 += ex1 * va.x + ex2 * vc.x;
        a1 += ex1 * va.y + ex2 * vc.y;
        a2 += ex1 * vb.x + ex2 * vd.x;
        a3 += ex1 * vb.y + ex2 * vd.y;
    }
    if (i < e_end) {
        int e1 = __ldg(&sorted[i]);
        int c1 = __ldg(&col[e1]);
        uint2 k1 = *((const uint2*)(K + (size_t)(c1 + koff) * HID) + lane);
        uint2 v1 = *((const uint2*)(V + (size_t)(c1 + koff) * HID) + lane);
        float2 ka = __bfloat1622float2(*(bf162*)&k1.x);
        float2 kb = __bfloat1622float2(*(bf162*)&k1.y);
        float d1 = qa.x * ka.x + qa.y * ka.y + qb.x * kb.x + qb.y * kb.y;
        d1 += __shfl_xor_sync(0xffffffffu, d1, 1);
        d1 += __shfl_xor_sync(0xffffffffu, d1, 2);
        float ex1 = __expf(d1 * SCALE + __ldg(&bias[(size_t)e1 * NHD + h]));
        z += ex1;
        float2 va = __bfloat1622float2(*(bf162*)&v1.x);
        float2 vb = __bfloat1622float2(*(bf162*)&v1.y);
        a0 += ex1 * va.x; a1 += ex1 * va.y;
        a2 += ex1 * vb.x; a3 += ex1 * vb.y;
    }

    float rz = 1.0f / (z + 1e-16f);
    *(float4*)(O + (size_t)orow * HID + lane * 4) =
        make_float4(a0 * rz, a1 * rz, a2 * rz, a3 * rz);
}

// ---------------- host ----------------
extern "C" void kernel_launch(void* const* d_in, const int* in_sizes, int n_in,
                              void* d_out, int out_size)
{
    const float* x_all    = (const float*)d_in[0];
    const float* bias_c2t = (const float*)d_in[1];
    const float* bias_t2c = (const float*)d_in[2];
    const int*   c2t_row  = (const int*)d_in[3];
    const int*   c2t_col  = (const int*)d_in[4];
    const int*   t2c_row  = (const int*)d_in[5];
    const int*   t2c_col  = (const int*)d_in[6];
    const float* ln1_g    = (const float*)d_in[7];
    const float* ln1_b    = (const float*)d_in[8];
    const float* Wq = (const float*)d_in[9];   const float* bq = (const float*)d_in[10];
    const float* Wk = (const float*)d_in[11];  const float* bk = (const float*)d_in[12];
    const float* Wv = (const float*)d_in[13];  const float* bv = (const float*)d_in[14];
    const float* Wo = (const float*)d_in[15];  const float* bo = (const float*)d_in[16];
    const float* ln2_g = (const float*)d_in[17];
    const float* ln2_b = (const float*)d_in[18];
    const float* W1 = (const float*)d_in[19];  const float* b1 = (const float*)d_in[20];
    const float* W2 = (const float*)d_in[21];  const float* b2 = (const float*)d_in[22];
    float* out = (float*)d_out;

    float *o;
    bf16 *qb, *kb, *vb;
    int *cnt, *start, *fill, *sorted, *bsum;
    cudaGetSymbolAddress((void**)&qb, g_qb);
    cudaGetSymbolAddress((void**)&kb, g_kb);
    cudaGetSymbolAddress((void**)&vb, g_vb);
    cudaGetSymbolAddress((void**)&o,  g_o);
    cudaGetSymbolAddress((void**)&cnt,    g_cnt);
    cudaGetSymbolAddress((void**)&start,  g_start);
    cudaGetSymbolAddress((void**)&fill,   g_fill);
    cudaGetSymbolAddress((void**)&sorted, g_sorted);
    cudaGetSymbolAddress((void**)&bsum,   g_bsum);

    cudaFuncSetAttribute(qkv_kernel,
                         cudaFuncAttributeMaxDynamicSharedMemorySize, QKV_SMEM);
    cudaFuncSetAttribute(tail_kernel,
                         cudaFuncAttributeMaxDynamicSharedMemorySize, TAIL_SMEM);

    const int gemmGrid = (NALL + 127) / 128;
    const int eGrid    = (EDG + 255) / 256;
    const int nb       = (NALL + 1023) / 1024;

    // LN1 + QKV
    qkv_kernel<<<gemmGrid, 256, QKV_SMEM>>>(x_all, ln1_g, ln1_b, Wq, Wk, Wv,
                                            bq, bk, bv, qb, kb, vb, NALL);

    // combined CSR build for both directions
    cudaMemsetAsync(cnt, 0, NALL * sizeof(int), 0);
    hist_kernel<<<eGrid, 256>>>(c2t_row, t2c_row, cnt);
    scan_reduce_kernel<<<nb, 256>>>(cnt, bsum, NALL);
    scan_bsum_kernel<<<1, 32>>>(bsum, nb);
    scan_final_kernel<<<nb, 256>>>(cnt, bsum, start, fill, NALL);
    scatter_kernel<<<eGrid, 256>>>(c2t_row, t2c_row, fill, sorted);

    // both attentions in one launch
    edge_agg_kernel<<<(NALL + 7) / 8, 256>>>(qb, kb, vb, c2t_col, t2c_col,
                                             bias_c2t, bias_t2c,
                                             start, cnt, sorted, o);

    // Wo + residual + LN2 + W1 + gelu + W2 + residual
    tail_kernel<<<gemmGrid, 256, TAIL_SMEM>>>(o, x_all, Wo, bo, ln2_g, ln2_b,
                                              W1, b1, W2, b2, out, NALL);
}